// round 9
// baseline (speedup 1.0000x reference)
#include <cuda_runtime.h>
#include <cuda_fp16.h>
#include <cuda_bf16.h>
#include <cstdint>

#define NN 100000
#define EE 1600000
#define HID 64
#define OC 32
#define EPSV 1e-5f
#define EB 6250          // hist blocks (EE/256)
#define SBLK 98          // scan blocks ((NN+1023)/1024)

// ---------------- scratch (device globals; zero-initialized at module load) ----------------
__device__ __half g_qh[(size_t)NN * HID];    // q in fp16 (128 B/node)
__device__ float  g_skip[(size_t)NN * HID];
__device__ float  g_x[(size_t)NN * HID];
__device__ __half g_kvh[(size_t)NN * 128];   // per node: k[64] halves then v[64] halves (256 B)
__device__ uint4  g_wf[3 * 4096];            // per layer: 4 sel x 4 kt x 8 nt x 32 lanes {bh0,bh1,bl0,bl1}

__device__ int g_cnt[NN];                    // zeroed by k_head at end of every call
__device__ int g_rowstart[NN + 1];
__device__ int g_cursor[NN];
__device__ int g_csrsrc[EE];
__device__ int g_bsum[128];

// ================= CSR: histogram =================
__global__ void k_hist(const int* __restrict__ ei) {
    int e = blockIdx.x * blockDim.x + threadIdx.x;
    if (e < EE) atomicAdd(&g_cnt[ei[EE + e]], 1);
}

// ================= W-frag prep (bf16 hi/lo, all 3 layers) =================
__global__ void k_wprep3(const float* __restrict__ Wq, const float* __restrict__ Wk,
                         const float* __restrict__ Wv, const float* __restrict__ Ws) {
    int t = blockIdx.x * blockDim.x + threadIdx.x;   // 3 * 4096
    if (t >= 3 * 4096) return;
    int lane  = t & 31;
    int nt    = (t >> 5) & 7;
    int kt    = (t >> 8) & 3;
    int sel   = (t >> 10) & 3;
    int layer = t >> 12;
    const float* Wb = (sel == 0) ? Wq : (sel == 1) ? Wk : (sel == 2) ? Wv : Ws;
    const float* W = Wb + (size_t)layer * HID * HID;
    int grp = lane >> 2, tig = lane & 3;
    int n  = nt * 8 + grp;
    int k0 = kt * 16 + tig * 2;

    float b00 = W[k0 * 64 + n],       b01 = W[(k0 + 1) * 64 + n];
    float b10 = W[(k0 + 8) * 64 + n], b11 = W[(k0 + 9) * 64 + n];

    __nv_bfloat162 h0 = __floats2bfloat162_rn(b00, b01);
    __nv_bfloat162 h1 = __floats2bfloat162_rn(b10, b11);
    __nv_bfloat162 l0 = __floats2bfloat162_rn(b00 - __bfloat162float(h0.x),
                                              b01 - __bfloat162float(h0.y));
    __nv_bfloat162 l1 = __floats2bfloat162_rn(b10 - __bfloat162float(h1.x),
                                              b11 - __bfloat162float(h1.y));
    uint4 o;
    o.x = *(uint32_t*)&h0; o.y = *(uint32_t*)&h1;
    o.z = *(uint32_t*)&l0; o.w = *(uint32_t*)&l1;
    g_wf[t] = o;
}

// ================= scan stage 1 =================
__global__ void k_scan1() {
    __shared__ int sh[1024];
    int i = blockIdx.x * 1024 + threadIdx.x;
    int v = (i < NN) ? g_cnt[i] : 0;
    sh[threadIdx.x] = v;
    __syncthreads();
    for (int off = 1; off < 1024; off <<= 1) {
        int t = (threadIdx.x >= off) ? sh[threadIdx.x - off] : 0;
        __syncthreads();
        sh[threadIdx.x] += t;
        __syncthreads();
    }
    if (i < NN) g_rowstart[i] = sh[threadIdx.x] - v;
    if (threadIdx.x == 1023) g_bsum[blockIdx.x] = sh[1023];
}

// ================= scan fixup =================
__global__ void k_scan_fix() {
    __shared__ int sh[128];
    int t = threadIdx.x;
    if (t < 128) sh[t] = (t < SBLK) ? g_bsum[t] : 0;
    __syncthreads();
    for (int off = 1; off < 128; off <<= 1) {
        int u = (t < 128 && t >= off) ? sh[t - off] : 0;
        __syncthreads();
        if (t < 128) sh[t] += u;
        __syncthreads();
    }
    __shared__ int pre[128];
    if (t < 128) pre[t] = sh[t] - ((t < SBLK) ? g_bsum[t] : 0);
    __syncthreads();
    int i = blockIdx.x * blockDim.x + t;
    if (i < NN) {
        int rs = g_rowstart[i] + pre[i >> 10];
        g_rowstart[i] = rs;
        g_cursor[i] = rs;
    }
    if (i == 0) g_rowstart[NN] = EE;
}

__global__ void k_scatter(const int* __restrict__ ei) {
    int e = blockIdx.x * blockDim.x + threadIdx.x;
    if (e >= EE) return;
    int s = ei[e], d = ei[EE + e];
    int pos = atomicAdd(&g_cursor[d], 1);
    g_csrsrc[pos] = s;
}

// ================= fused QKVS GEMM: pre-split bf16 hi/lo smem, 32 rows/block =================
__device__ __forceinline__ void mma_bf16(float* c, uint32_t a0, uint32_t a1,
                                         uint32_t a2, uint32_t a3,
                                         uint32_t b0, uint32_t b1) {
    asm volatile("mma.sync.aligned.m16n8k16.row.col.f32.bf16.bf16.f32 "
                 "{%0,%1,%2,%3}, {%4,%5,%6,%7}, {%8,%9}, {%0,%1,%2,%3};"
                 : "+f"(c[0]), "+f"(c[1]), "+f"(c[2]), "+f"(c[3])
                 : "r"(a0), "r"(a1), "r"(a2), "r"(a3), "r"(b0), "r"(b1));
}

__device__ __forceinline__ uint32_t pack_hi(float a, float b) {
    __nv_bfloat162 h = __floats2bfloat162_rn(a, b);
    return *(uint32_t*)&h;
}
__device__ __forceinline__ uint32_t pack_lo(float a, float b, uint32_t hi) {
    __nv_bfloat162 h = *(__nv_bfloat162*)&hi;
    __nv_bfloat162 l = __floats2bfloat162_rn(a - __bfloat162float(h.x),
                                             b - __bfloat162float(h.y));
    return *(uint32_t*)&l;
}

#define XSTR 72   // bf16 row stride: conflict-free

__global__ void __launch_bounds__(256, 2) k_gemm_fused(
        const float* __restrict__ xin, const uint4* __restrict__ wf,
        const float* __restrict__ bq, const float* __restrict__ bk,
        const float* __restrict__ bv, const float* __restrict__ bs) {
    __shared__ __nv_bfloat16 xh[32 * XSTR];
    __shared__ __nv_bfloat16 xl[32 * XSTR];
    const float* x = xin ? xin : g_x;
    int row0 = blockIdx.x * 32;
    int t = threadIdx.x;

#pragma unroll
    for (int i = 0; i < 2; i++) {
        int idx = t + 256 * i;
        int r = idx >> 4, c4 = idx & 15;
        float4 val = ((const float4*)(x + (size_t)(row0 + r) * 64))[c4];
        uint32_t h01 = pack_hi(val.x, val.y);
        uint32_t h23 = pack_hi(val.z, val.w);
        uint32_t l01 = pack_lo(val.x, val.y, h01);
        uint32_t l23 = pack_lo(val.z, val.w, h23);
        *(uint2*)(&xh[r * XSTR + c4 * 4]) = make_uint2(h01, h23);
        *(uint2*)(&xl[r * XSTR + c4 * 4]) = make_uint2(l01, l23);
    }
    __syncthreads();

    int wid = t >> 5, lane = t & 31;
    int tig = lane & 3, grp = lane >> 2;
    int cloc = wid * 8 + 2 * tig;

    float acc[4][2][4];
    {
        const float* biases[4] = {bq, bk, bv, bs};
#pragma unroll
        for (int sel = 0; sel < 4; sel++) {
            float b0 = biases[sel][cloc], b1 = biases[sel][cloc + 1];
#pragma unroll
            for (int mt = 0; mt < 2; mt++) {
                acc[sel][mt][0] = b0; acc[sel][mt][1] = b1;
                acc[sel][mt][2] = b0; acc[sel][mt][3] = b1;
            }
        }
    }

#pragma unroll
    for (int kt = 0; kt < 4; kt++) {
        uint4 bf[4];
#pragma unroll
        for (int sel = 0; sel < 4; sel++)
            bf[sel] = wf[((sel * 4 + kt) * 8 + wid) * 32 + lane];
        int k = kt * 16 + tig * 2;
#pragma unroll
        for (int mt = 0; mt < 2; mt++) {
            int r = mt * 16 + grp;
            uint32_t h0 = *(uint32_t*)&xh[r * XSTR + k];
            uint32_t h1 = *(uint32_t*)&xh[(r + 8) * XSTR + k];
            uint32_t h2 = *(uint32_t*)&xh[r * XSTR + k + 8];
            uint32_t h3 = *(uint32_t*)&xh[(r + 8) * XSTR + k + 8];
            uint32_t l0 = *(uint32_t*)&xl[r * XSTR + k];
            uint32_t l1 = *(uint32_t*)&xl[(r + 8) * XSTR + k];
            uint32_t l2 = *(uint32_t*)&xl[r * XSTR + k + 8];
            uint32_t l3 = *(uint32_t*)&xl[(r + 8) * XSTR + k + 8];
#pragma unroll
            for (int sel = 0; sel < 4; sel++) {
                mma_bf16(acc[sel][mt], h0, h1, h2, h3, bf[sel].x, bf[sel].y);
                mma_bf16(acc[sel][mt], h0, h1, h2, h3, bf[sel].z, bf[sel].w);
                mma_bf16(acc[sel][mt], l0, l1, l2, l3, bf[sel].x, bf[sel].y);
            }
        }
    }

#pragma unroll
    for (int sel = 0; sel < 4; sel++) {
#pragma unroll
        for (int mt = 0; mt < 2; mt++) {
            int r0g = row0 + mt * 16 + grp;
            int r1g = r0g + 8;
            float* a = acc[sel][mt];
            if (sel == 0) {
                *(__half2*)(g_qh + (size_t)r0g * 64 + cloc) = __floats2half2_rn(a[0], a[1]);
                *(__half2*)(g_qh + (size_t)r1g * 64 + cloc) = __floats2half2_rn(a[2], a[3]);
            } else if (sel == 3) {
                *(float2*)(g_skip + (size_t)r0g * 64 + cloc) = make_float2(a[0], a[1]);
                *(float2*)(g_skip + (size_t)r1g * 64 + cloc) = make_float2(a[2], a[3]);
            } else {
                int off = (sel == 2) ? 64 : 0;
                *(__half2*)(g_kvh + (size_t)r0g * 128 + off + cloc) = __floats2half2_rn(a[0], a[1]);
                *(__half2*)(g_kvh + (size_t)r1g * 128 + off + cloc) = __floats2half2_rn(a[2], a[3]);
            }
        }
    }
}

// ================= fused attention: uniform masked 16-edge batches, fp16 q =================
__device__ __forceinline__ float dot8(const float4& qa, const float4& qb, const uint4& kk) {
    float2 k0 = __half22float2(*(__half2*)&kk.x);
    float2 k1 = __half22float2(*(__half2*)&kk.y);
    float2 k2 = __half22float2(*(__half2*)&kk.z);
    float2 k3 = __half22float2(*(__half2*)&kk.w);
    return qa.x * k0.x + qa.y * k0.y + qa.z * k1.x + qa.w * k1.y
         + qb.x * k2.x + qb.y * k2.y + qb.z * k3.x + qb.w * k3.y;
}
__device__ __forceinline__ void acc8(float* a, float ex, const uint4& vv) {
    float2 v0 = __half22float2(*(__half2*)&vv.x);
    float2 v1 = __half22float2(*(__half2*)&vv.y);
    float2 v2 = __half22float2(*(__half2*)&vv.z);
    float2 v3 = __half22float2(*(__half2*)&vv.w);
    a[0] = fmaf(ex, v0.x, a[0]); a[1] = fmaf(ex, v0.y, a[1]);
    a[2] = fmaf(ex, v1.x, a[2]); a[3] = fmaf(ex, v1.y, a[3]);
    a[4] = fmaf(ex, v2.x, a[4]); a[5] = fmaf(ex, v2.y, a[5]);
    a[6] = fmaf(ex, v3.x, a[6]); a[7] = fmaf(ex, v3.y, a[7]);
}

__global__ void k_attn(const float* __restrict__ bg, const float* __restrict__ bb,
                       const float* __restrict__ bm, const float* __restrict__ bvv) {
    int warp = (blockIdx.x * blockDim.x + threadIdx.x) >> 5;
    if (warp >= NN) return;
    int lane = threadIdx.x & 31;
    int g = lane >> 3, j = lane & 7;
    int node = warp;

    uint4 qq = ((const uint4*)(g_qh + (size_t)node * 64))[j];
    float2 q0 = __half22float2(*(__half2*)&qq.x);
    float2 q1 = __half22float2(*(__half2*)&qq.y);
    float2 q2 = __half22float2(*(__half2*)&qq.z);
    float2 q3 = __half22float2(*(__half2*)&qq.w);
    float4 qa = make_float4(q0.x, q0.y, q1.x, q1.y);
    float4 qb = make_float4(q2.x, q2.y, q3.x, q3.y);

    int beg = g_rowstart[node];
    int end = g_rowstart[node + 1];

    float a[8] = {0.f, 0.f, 0.f, 0.f, 0.f, 0.f, 0.f, 0.f};
    float den = 0.f;
    int lim = end - 1;

    for (int i = beg; i < end; i += 16) {
        int iA = i + g, iB = i + 4 + g, iC = i + 8 + g, iD = i + 12 + g;
        int sA = g_csrsrc[min(iA, lim)];
        int sB = g_csrsrc[min(iB, lim)];
        int sC = g_csrsrc[min(iC, lim)];
        int sD = g_csrsrc[min(iD, lim)];
        const uint4* kvA = (const uint4*)(g_kvh + (size_t)sA * 128);
        const uint4* kvB = (const uint4*)(g_kvh + (size_t)sB * 128);
        const uint4* kvC = (const uint4*)(g_kvh + (size_t)sC * 128);
        const uint4* kvD = (const uint4*)(g_kvh + (size_t)sD * 128);
        uint4 kA = kvA[j], kB = kvB[j], kC = kvC[j], kD = kvD[j];
        uint4 vA = kvA[8 + j], vB = kvB[8 + j], vC = kvC[8 + j], vD = kvD[8 + j];

        float pA = dot8(qa, qb, kA);
        float pB = dot8(qa, qb, kB);
        float pC = dot8(qa, qb, kC);
        float pD = dot8(qa, qb, kD);
        pA += __shfl_xor_sync(0xffffffffu, pA, 1);
        pB += __shfl_xor_sync(0xffffffffu, pB, 1);
        pC += __shfl_xor_sync(0xffffffffu, pC, 1);
        pD += __shfl_xor_sync(0xffffffffu, pD, 1);
        float eA = (iA < end) ? __expf(pA * 0.25f) : 0.f;
        float eB = (iB < end) ? __expf(pB * 0.25f) : 0.f;
        float eC = (iC < end) ? __expf(pC * 0.25f) : 0.f;
        float eD = (iD < end) ? __expf(pD * 0.25f) : 0.f;
        acc8(a, eA, vA);
        acc8(a, eB, vB);
        acc8(a, eC, vC);
        acc8(a, eD, vD);
        den += (eA + eB) + (eC + eD);
    }

#pragma unroll
    for (int c = 0; c < 8; c++) {
        a[c] += __shfl_xor_sync(0xffffffffu, a[c], 8);
        a[c] += __shfl_xor_sync(0xffffffffu, a[c], 16);
    }
    den += __shfl_xor_sync(0xffffffffu, den, 8);
    den += __shfl_xor_sync(0xffffffffu, den, 16);

    if (g == 0) {
        float inv = (den > 0.f) ? __frcp_rn(den) : 0.f;
        float4 ska = ((const float4*)(g_skip + (size_t)node * 64))[2 * j];
        float4 skb = ((const float4*)(g_skip + (size_t)node * 64))[2 * j + 1];
        float4 bga = ((const float4*)bg)[2 * j],  bgb = ((const float4*)bg)[2 * j + 1];
        float4 bba = ((const float4*)bb)[2 * j],  bbb = ((const float4*)bb)[2 * j + 1];
        float4 bma = ((const float4*)bm)[2 * j],  bmb = ((const float4*)bm)[2 * j + 1];
        float4 bva = ((const float4*)bvv)[2 * j], bvb = ((const float4*)bvv)[2 * j + 1];
        float o[8];
        o[0] = a[0] * inv + ska.x; o[1] = a[1] * inv + ska.y;
        o[2] = a[2] * inv + ska.z; o[3] = a[3] * inv + ska.w;
        o[4] = a[4] * inv + skb.x; o[5] = a[5] * inv + skb.y;
        o[6] = a[6] * inv + skb.z; o[7] = a[7] * inv + skb.w;
        o[0] = fmaxf((o[0] - bma.x) * rsqrtf(bva.x + EPSV) * bga.x + bba.x, 0.f);
        o[1] = fmaxf((o[1] - bma.y) * rsqrtf(bva.y + EPSV) * bga.y + bba.y, 0.f);
        o[2] = fmaxf((o[2] - bma.z) * rsqrtf(bva.z + EPSV) * bga.z + bba.z, 0.f);
        o[3] = fmaxf((o[3] - bma.w) * rsqrtf(bva.w + EPSV) * bga.w + bba.w, 0.f);
        o[4] = fmaxf((o[4] - bmb.x) * rsqrtf(bvb.x + EPSV) * bgb.x + bbb.x, 0.f);
        o[5] = fmaxf((o[5] - bmb.y) * rsqrtf(bvb.y + EPSV) * bgb.y + bbb.y, 0.f);
        o[6] = fmaxf((o[6] - bmb.z) * rsqrtf(bvb.z + EPSV) * bgb.z + bbb.z, 0.f);
        o[7] = fmaxf((o[7] - bmb.w) * rsqrtf(bvb.w + EPSV) * bgb.w + bbb.w, 0.f);
        float4* xo = (float4*)(g_x + (size_t)node * 64);
        xo[2 * j]     = make_float4(o[0], o[1], o[2], o[3]);
        xo[2 * j + 1] = make_float4(o[4], o[5], o[6], o[7]);
    }
}

// ================= head GEMM (also re-zeros g_cnt for the next call) =================
__global__ void k_head(const float* __restrict__ Wh, const float* __restrict__ bh,
                       float* __restrict__ out) {
    __shared__ float xs[32 * 64];
    __shared__ float ws[64 * 32];
    int t = threadIdx.x;
    int gid = blockIdx.x * blockDim.x + t;
    if (gid < NN) g_cnt[gid] = 0;            // prep histogram for next call
    int node0 = blockIdx.x * 32;
    const float4* xsrc = (const float4*)(g_x + (size_t)node0 * 64);
    ((float4*)xs)[t]       = xsrc[t];
    ((float4*)xs)[t + 256] = xsrc[t + 256];
    ((float4*)ws)[t]       = ((const float4*)Wh)[t];
    ((float4*)ws)[t + 256] = ((const float4*)Wh)[t + 256];
    __syncthreads();
    int col = t & 31, nr = t >> 5;
    float a0, a1, a2, a3;
    a0 = a1 = a2 = a3 = bh[col];
#pragma unroll 8
    for (int kk = 0; kk < 64; kk++) {
        float w = ws[kk * 32 + col];
        a0 = fmaf(xs[nr * 64 + kk],        w, a0);
        a1 = fmaf(xs[(nr + 8) * 64 + kk],  w, a1);
        a2 = fmaf(xs[(nr + 16) * 64 + kk], w, a2);
        a3 = fmaf(xs[(nr + 24) * 64 + kk], w, a3);
    }
    out[(size_t)(node0 + nr) * 32 + col]      = a0;
    out[(size_t)(node0 + nr + 8) * 32 + col]  = a1;
    out[(size_t)(node0 + nr + 16) * 32 + col] = a2;
    out[(size_t)(node0 + nr + 24) * 32 + col] = a3;
}

// ================= launch =================
static cudaStream_t g_s2 = nullptr;
static cudaEvent_t  g_evA = nullptr, g_evB = nullptr;
static int g_inited = 0;

extern "C" void kernel_launch(void* const* d_in, const int* in_sizes, int n_in,
                              void* d_out, int out_size) {
    const float* x    = (const float*)d_in[0];
    const int*   ei   = (const int*)  d_in[1];
    const float* Wq   = (const float*)d_in[2];
    const float* bq   = (const float*)d_in[3];
    const float* Wk   = (const float*)d_in[4];
    const float* bk   = (const float*)d_in[5];
    const float* Wv   = (const float*)d_in[6];
    const float* bv   = (const float*)d_in[7];
    const float* Ws   = (const float*)d_in[8];
    const float* bs   = (const float*)d_in[9];
    const float* bn_g = (const float*)d_in[10];
    const float* bn_b = (const float*)d_in[11];
    const float* bn_m = (const float*)d_in[12];
    const float* bn_v = (const float*)d_in[13];
    const float* Wh   = (const float*)d_in[14];
    const float* bh   = (const float*)d_in[15];
    float* out = (float*)d_out;

    const int NB = (NN + 255) / 256;           // 391
    const int GA = (NN * 32 + 255) / 256;      // warp per node
    const int GH = NN / 32;                    // 3125
    const int GR = NN / 32;                    // 3125 (exact)

    uint4* wf_base;
    cudaGetSymbolAddress((void**)&wf_base, g_wf);

    // One-time stream/event setup (runs on the first, non-captured, correctness
    // call; same launches every call — work is identical and deterministic).
    if (!g_inited) {
        g_inited = 1;
        if (cudaStreamCreateWithFlags(&g_s2, cudaStreamNonBlocking) != cudaSuccess) {
            g_s2 = nullptr;
        } else if (cudaEventCreateWithFlags(&g_evA, cudaEventDisableTiming) != cudaSuccess ||
                   cudaEventCreateWithFlags(&g_evB, cudaEventDisableTiming) != cudaSuccess) {
            g_s2 = nullptr;
        }
    }

    if (g_s2) {
        // Fork: CSR build on s2 concurrent with wprep + gemm L0 on main stream.
        cudaEventRecord(g_evA, 0);
        cudaStreamWaitEvent(g_s2, g_evA, 0);
        k_hist<<<EB, 256, 0, g_s2>>>(ei);
        k_scan1<<<SBLK, 1024, 0, g_s2>>>();
        k_scan_fix<<<NB, 256, 0, g_s2>>>();
        k_scatter<<<EB, 256, 0, g_s2>>>(ei);
        cudaEventRecord(g_evB, g_s2);

        k_wprep3<<<48, 256>>>(Wq, Wk, Wv, Ws);
        k_gemm_fused<<<GR, 256>>>(x, wf_base, bq, bk, bv, bs);

        cudaStreamWaitEvent(0, g_evB, 0);      // join before attn
    } else {
        // Serial fallback
        k_wprep3<<<48, 256>>>(Wq, Wk, Wv, Ws);
        k_hist<<<EB, 256>>>(ei);
        k_scan1<<<SBLK, 1024>>>();
        k_scan_fix<<<NB, 256>>>();
        k_scatter<<<EB, 256>>>(ei);
        k_gemm_fused<<<GR, 256>>>(x, wf_base, bq, bk, bv, bs);
    }

    k_attn<<<GA, 256>>>(bn_g, bn_b, bn_m, bn_v);

    for (int l = 1; l < 3; l++) {
        size_t bo = (size_t)l * HID;
        k_gemm_fused<<<GR, 256>>>(nullptr, wf_base + (size_t)l * 4096,
                                  bq + bo, bk + bo, bv + bo, bs + bo);
        k_attn<<<GA, 256>>>(bn_g + bo, bn_b + bo, bn_m + bo, bn_v + bo);
    }
    k_head<<<GH, 256>>>(Wh, bh, out);
}

// round 11
// speedup vs baseline: 1.0372x; 1.0372x over previous
#include <cuda_runtime.h>
#include <cuda_fp16.h>
#include <cuda_bf16.h>
#include <cstdint>

#define NN 100000
#define EE 1600000
#define HID 64
#define OC 32
#define EPSV 1e-5f
#define EB 6250          // hist/scatter blocks (EE/256)
#define WPREPB 48        // wprep blocks (3*4096/256)
#define SBLK 98          // scan blocks ((NN+1023)/1024)
#define GR 3125          // gemm blocks (NN/32, exact)

// ---------------- scratch (device globals; zero-initialized at module load) ----------------
__device__ __half g_qh[(size_t)NN * HID];    // q in fp16 (128 B/node)
__device__ float  g_skip[(size_t)NN * HID];
__device__ float  g_x[(size_t)NN * HID];
__device__ __half g_kvh[(size_t)NN * 128];   // per node: k[64] halves then v[64] halves (256 B)
__device__ uint4  g_wf[3 * 4096];            // per layer: 4 sel x 4 kt x 8 nt x 32 lanes {bh0,bh1,bl0,bl1}

__device__ int g_cnt[NN];                    // zeroed by k_head at end of every call
__device__ int g_rowstart[NN + 1];
__device__ int g_cursor[NN];
__device__ int g_csrsrc[EE];
__device__ int g_bsum[128];

// ================= GEMM helpers =================
__device__ __forceinline__ void mma_bf16(float* c, uint32_t a0, uint32_t a1,
                                         uint32_t a2, uint32_t a3,
                                         uint32_t b0, uint32_t b1) {
    asm volatile("mma.sync.aligned.m16n8k16.row.col.f32.bf16.bf16.f32 "
                 "{%0,%1,%2,%3}, {%4,%5,%6,%7}, {%8,%9}, {%0,%1,%2,%3};"
                 : "+f"(c[0]), "+f"(c[1]), "+f"(c[2]), "+f"(c[3])
                 : "r"(a0), "r"(a1), "r"(a2), "r"(a3), "r"(b0), "r"(b1));
}
__device__ __forceinline__ uint32_t pack_hi(float a, float b) {
    __nv_bfloat162 h = __floats2bfloat162_rn(a, b);
    return *(uint32_t*)&h;
}
__device__ __forceinline__ uint32_t pack_lo(float a, float b, uint32_t hi) {
    __nv_bfloat162 h = *(__nv_bfloat162*)&hi;
    __nv_bfloat162 l = __floats2bfloat162_rn(a - __bfloat162float(h.x),
                                             b - __bfloat162float(h.y));
    return *(uint32_t*)&l;
}

#define XSTR 72   // bf16 row stride: conflict-free

// gemm body: computes 32 rows starting at row0 for all 4 output matrices.
__device__ __forceinline__ void gemm_body(
        const float* __restrict__ x, const uint4* __restrict__ wf, int row0,
        const float* __restrict__ bq, const float* __restrict__ bk,
        const float* __restrict__ bv, const float* __restrict__ bs,
        __nv_bfloat16* xh, __nv_bfloat16* xl) {
    int t = threadIdx.x;
#pragma unroll
    for (int i = 0; i < 2; i++) {
        int idx = t + 256 * i;
        int r = idx >> 4, c4 = idx & 15;
        float4 val = ((const float4*)(x + (size_t)(row0 + r) * 64))[c4];
        uint32_t h01 = pack_hi(val.x, val.y);
        uint32_t h23 = pack_hi(val.z, val.w);
        uint32_t l01 = pack_lo(val.x, val.y, h01);
        uint32_t l23 = pack_lo(val.z, val.w, h23);
        *(uint2*)(&xh[r * XSTR + c4 * 4]) = make_uint2(h01, h23);
        *(uint2*)(&xl[r * XSTR + c4 * 4]) = make_uint2(l01, l23);
    }
    __syncthreads();

    int wid = t >> 5, lane = t & 31;
    int tig = lane & 3, grp = lane >> 2;
    int cloc = wid * 8 + 2 * tig;

    float acc[4][2][4];
    {
        const float* biases[4] = {bq, bk, bv, bs};
#pragma unroll
        for (int sel = 0; sel < 4; sel++) {
            float b0 = biases[sel][cloc], b1 = biases[sel][cloc + 1];
#pragma unroll
            for (int mt = 0; mt < 2; mt++) {
                acc[sel][mt][0] = b0; acc[sel][mt][1] = b1;
                acc[sel][mt][2] = b0; acc[sel][mt][3] = b1;
            }
        }
    }

#pragma unroll
    for (int kt = 0; kt < 4; kt++) {
        uint4 bf[4];
#pragma unroll
        for (int sel = 0; sel < 4; sel++)
            bf[sel] = wf[((sel * 4 + kt) * 8 + wid) * 32 + lane];
        int k = kt * 16 + tig * 2;
#pragma unroll
        for (int mt = 0; mt < 2; mt++) {
            int r = mt * 16 + grp;
            uint32_t h0 = *(uint32_t*)&xh[r * XSTR + k];
            uint32_t h1 = *(uint32_t*)&xh[(r + 8) * XSTR + k];
            uint32_t h2 = *(uint32_t*)&xh[r * XSTR + k + 8];
            uint32_t h3 = *(uint32_t*)&xh[(r + 8) * XSTR + k + 8];
            uint32_t l0 = *(uint32_t*)&xl[r * XSTR + k];
            uint32_t l1 = *(uint32_t*)&xl[(r + 8) * XSTR + k];
            uint32_t l2 = *(uint32_t*)&xl[r * XSTR + k + 8];
            uint32_t l3 = *(uint32_t*)&xl[(r + 8) * XSTR + k + 8];
#pragma unroll
            for (int sel = 0; sel < 4; sel++) {
                mma_bf16(acc[sel][mt], h0, h1, h2, h3, bf[sel].x, bf[sel].y);
                mma_bf16(acc[sel][mt], h0, h1, h2, h3, bf[sel].z, bf[sel].w);
                mma_bf16(acc[sel][mt], l0, l1, l2, l3, bf[sel].x, bf[sel].y);
            }
        }
    }

#pragma unroll
    for (int sel = 0; sel < 4; sel++) {
#pragma unroll
        for (int mt = 0; mt < 2; mt++) {
            int r0g = row0 + mt * 16 + grp;
            int r1g = r0g + 8;
            float* a = acc[sel][mt];
            if (sel == 0) {
                *(__half2*)(g_qh + (size_t)r0g * 64 + cloc) = __floats2half2_rn(a[0], a[1]);
                *(__half2*)(g_qh + (size_t)r1g * 64 + cloc) = __floats2half2_rn(a[2], a[3]);
            } else if (sel == 3) {
                *(float2*)(g_skip + (size_t)r0g * 64 + cloc) = make_float2(a[0], a[1]);
                *(float2*)(g_skip + (size_t)r1g * 64 + cloc) = make_float2(a[2], a[3]);
            } else {
                int off = (sel == 2) ? 64 : 0;
                *(__half2*)(g_kvh + (size_t)r0g * 128 + off + cloc) = __floats2half2_rn(a[0], a[1]);
                *(__half2*)(g_kvh + (size_t)r1g * 128 + off + cloc) = __floats2half2_rn(a[2], a[3]);
            }
        }
    }
}

// ================= launch 1: hist + W-frag prep (disjoint block ranges) =================
__global__ void k_prep1(const int* __restrict__ ei,
                        const float* __restrict__ Wq, const float* __restrict__ Wk,
                        const float* __restrict__ Wv, const float* __restrict__ Ws) {
    int b = blockIdx.x;
    if (b < EB) {
        int e = b * 256 + threadIdx.x;
        if (e < EE) atomicAdd(&g_cnt[ei[EE + e]], 1);
        return;
    }
    int t = (b - EB) * 256 + threadIdx.x;
    if (t >= 3 * 4096) return;
    int lane  = t & 31;
    int nt    = (t >> 5) & 7;
    int kt    = (t >> 8) & 3;
    int sel   = (t >> 10) & 3;
    int layer = t >> 12;
    const float* Wb = (sel == 0) ? Wq : (sel == 1) ? Wk : (sel == 2) ? Wv : Ws;
    const float* W = Wb + (size_t)layer * HID * HID;
    int grp = lane >> 2, tig = lane & 3;
    int n  = nt * 8 + grp;
    int k0 = kt * 16 + tig * 2;
    float b00 = W[k0 * 64 + n],       b01 = W[(k0 + 1) * 64 + n];
    float b10 = W[(k0 + 8) * 64 + n], b11 = W[(k0 + 9) * 64 + n];
    uint32_t h0 = pack_hi(b00, b01), h1 = pack_hi(b10, b11);
    uint32_t l0 = pack_lo(b00, b01, h0), l1 = pack_lo(b10, b11, h1);
    uint4 o; o.x = h0; o.y = h1; o.z = l0; o.w = l1;
    g_wf[t] = o;
}

// ================= launch 2: scan stage 1 =================
__global__ void k_scan1() {
    __shared__ int sh[1024];
    int i = blockIdx.x * 1024 + threadIdx.x;
    int v = (i < NN) ? g_cnt[i] : 0;
    sh[threadIdx.x] = v;
    __syncthreads();
    for (int off = 1; off < 1024; off <<= 1) {
        int t = (threadIdx.x >= off) ? sh[threadIdx.x - off] : 0;
        __syncthreads();
        sh[threadIdx.x] += t;
        __syncthreads();
    }
    if (i < NN) g_rowstart[i] = sh[threadIdx.x] - v;
    if (threadIdx.x == 1023) g_bsum[blockIdx.x] = sh[1023];
}

// ================= launch 3: scan fixup =================
__global__ void k_scan_fix() {
    __shared__ int sh[128];
    int t = threadIdx.x;
    if (t < 128) sh[t] = (t < SBLK) ? g_bsum[t] : 0;
    __syncthreads();
    for (int off = 1; off < 128; off <<= 1) {
        int u = (t < 128 && t >= off) ? sh[t - off] : 0;
        __syncthreads();
        if (t < 128) sh[t] += u;
        __syncthreads();
    }
    __shared__ int pre[128];
    if (t < 128) pre[t] = sh[t] - ((t < SBLK) ? g_bsum[t] : 0);
    __syncthreads();
    int i = blockIdx.x * blockDim.x + t;
    if (i < NN) {
        int rs = g_rowstart[i] + pre[i >> 10];
        g_rowstart[i] = rs;
        g_cursor[i] = rs;
    }
    if (i == 0) g_rowstart[NN] = EE;
}

// ================= launch 4: fused gemm L0 + scatter (disjoint block ranges) =================
// blocks [0,GR): gemm L0; blocks [GR, GR+EB): scatter. Gemm first so the heavy
// CTAs schedule immediately; latency-bound scatter blocks backfill SM slots.
__global__ void __launch_bounds__(256, 2) k_gemm_scatter(
        const float* __restrict__ x, const uint4* __restrict__ wf,
        const float* __restrict__ bq, const float* __restrict__ bk,
        const float* __restrict__ bv, const float* __restrict__ bs,
        const int* __restrict__ ei) {
    __shared__ __nv_bfloat16 xh[32 * XSTR];
    __shared__ __nv_bfloat16 xl[32 * XSTR];
    int b = blockIdx.x;
    if (b >= GR) {
        int e = (b - GR) * 256 + threadIdx.x;
        if (e < EE) {
            int s = ei[e], d = ei[EE + e];
            int pos = atomicAdd(&g_cursor[d], 1);
            g_csrsrc[pos] = s;
        }
        return;
    }
    gemm_body(x, wf, b * 32, bq, bk, bv, bs, xh, xl);
}

// ================= layer 1/2 gemm =================
__global__ void __launch_bounds__(256, 2) k_gemm_fused(
        const uint4* __restrict__ wf,
        const float* __restrict__ bq, const float* __restrict__ bk,
        const float* __restrict__ bv, const float* __restrict__ bs) {
    __shared__ __nv_bfloat16 xh[32 * XSTR];
    __shared__ __nv_bfloat16 xl[32 * XSTR];
    gemm_body(g_x, wf, blockIdx.x * 32, bq, bk, bv, bs, xh, xl);
}

// ================= fused attention: 16-edge batches + index prefetch =================
__device__ __forceinline__ float dot8(const float4& qa, const float4& qb, const uint4& kk) {
    float2 k0 = __half22float2(*(__half2*)&kk.x);
    float2 k1 = __half22float2(*(__half2*)&kk.y);
    float2 k2 = __half22float2(*(__half2*)&kk.z);
    float2 k3 = __half22float2(*(__half2*)&kk.w);
    return qa.x * k0.x + qa.y * k0.y + qa.z * k1.x + qa.w * k1.y
         + qb.x * k2.x + qb.y * k2.y + qb.z * k3.x + qb.w * k3.y;
}
__device__ __forceinline__ void acc8(float* a, float ex, const uint4& vv) {
    float2 v0 = __half22float2(*(__half2*)&vv.x);
    float2 v1 = __half22float2(*(__half2*)&vv.y);
    float2 v2 = __half22float2(*(__half2*)&vv.z);
    float2 v3 = __half22float2(*(__half2*)&vv.w);
    a[0] = fmaf(ex, v0.x, a[0]); a[1] = fmaf(ex, v0.y, a[1]);
    a[2] = fmaf(ex, v1.x, a[2]); a[3] = fmaf(ex, v1.y, a[3]);
    a[4] = fmaf(ex, v2.x, a[4]); a[5] = fmaf(ex, v2.y, a[5]);
    a[6] = fmaf(ex, v3.x, a[6]); a[7] = fmaf(ex, v3.y, a[7]);
}

__global__ void k_attn(const float* __restrict__ bg, const float* __restrict__ bb,
                       const float* __restrict__ bm, const float* __restrict__ bvv) {
    int warp = (blockIdx.x * blockDim.x + threadIdx.x) >> 5;
    if (warp >= NN) return;
    int lane = threadIdx.x & 31;
    int g = lane >> 3, j = lane & 7;
    int node = warp;

    uint4 qq = ((const uint4*)(g_qh + (size_t)node * 64))[j];
    float2 q0 = __half22float2(*(__half2*)&qq.x);
    float2 q1 = __half22float2(*(__half2*)&qq.y);
    float2 q2 = __half22float2(*(__half2*)&qq.z);
    float2 q3 = __half22float2(*(__half2*)&qq.w);
    float4 qa = make_float4(q0.x, q0.y, q1.x, q1.y);
    float4 qb = make_float4(q2.x, q2.y, q3.x, q3.y);

    int beg = g_rowstart[node];
    int end = g_rowstart[node + 1];

    float a[8] = {0.f, 0.f, 0.f, 0.f, 0.f, 0.f, 0.f, 0.f};
    float den = 0.f;

    if (beg < end) {
        int lim = end - 1;
        int nA = g_csrsrc[min(beg + g, lim)];
        int nB = g_csrsrc[min(beg + 4 + g, lim)];
        int nC = g_csrsrc[min(beg + 8 + g, lim)];
        int nD = g_csrsrc[min(beg + 12 + g, lim)];
        for (int i = beg; i < end; i += 16) {
            int sA = nA, sB = nB, sC = nC, sD = nD;
            int ni = i + 16;
            nA = g_csrsrc[min(ni + g, lim)];
            nB = g_csrsrc[min(ni + 4 + g, lim)];
            nC = g_csrsrc[min(ni + 8 + g, lim)];
            nD = g_csrsrc[min(ni + 12 + g, lim)];

            const uint4* kvA = (const uint4*)(g_kvh + (size_t)sA * 128);
            const uint4* kvB = (const uint4*)(g_kvh + (size_t)sB * 128);
            const uint4* kvC = (const uint4*)(g_kvh + (size_t)sC * 128);
            const uint4* kvD = (const uint4*)(g_kvh + (size_t)sD * 128);
            uint4 kA = kvA[j], kB = kvB[j], kC = kvC[j], kD = kvD[j];
            uint4 vA = kvA[8 + j], vB = kvB[8 + j], vC = kvC[8 + j], vD = kvD[8 + j];

            float pA = dot8(qa, qb, kA);
            float pB = dot8(qa, qb, kB);
            float pC = dot8(qa, qb, kC);
            float pD = dot8(qa, qb, kD);
            pA += __shfl_xor_sync(0xffffffffu, pA, 1);
            pB += __shfl_xor_sync(0xffffffffu, pB, 1);
            pC += __shfl_xor_sync(0xffffffffu, pC, 1);
            pD += __shfl_xor_sync(0xffffffffu, pD, 1);
            float eA = (i + g < end)      ? __expf(pA * 0.25f) : 0.f;
            float eB = (i + 4 + g < end)  ? __expf(pB * 0.25f) : 0.f;
            float eC = (i + 8 + g < end)  ? __expf(pC * 0.25f) : 0.f;
            float eD = (i + 12 + g < end) ? __expf(pD * 0.25f) : 0.f;
            acc8(a, eA, vA);
            acc8(a, eB, vB);
            acc8(a, eC, vC);
            acc8(a, eD, vD);
            den += (eA + eB) + (eC + eD);
        }
    }

#pragma unroll
    for (int c = 0; c < 8; c++) {
        a[c] += __shfl_xor_sync(0xffffffffu, a[c], 8);
        a[c] += __shfl_xor_sync(0xffffffffu, a[c], 16);
    }
    den += __shfl_xor_sync(0xffffffffu, den, 8);
    den += __shfl_xor_sync(0xffffffffu, den, 16);

    if (g == 0) {
        float inv = (den > 0.f) ? __frcp_rn(den) : 0.f;
        float4 ska = ((const float4*)(g_skip + (size_t)node * 64))[2 * j];
        float4 skb = ((const float4*)(g_skip + (size_t)node * 64))[2 * j + 1];
        float4 bga = ((const float4*)bg)[2 * j],  bgb = ((const float4*)bg)[2 * j + 1];
        float4 bba = ((const float4*)bb)[2 * j],  bbb = ((const float4*)bb)[2 * j + 1];
        float4 bma = ((const float4*)bm)[2 * j],  bmb = ((const float4*)bm)[2 * j + 1];
        float4 bva = ((const float4*)bvv)[2 * j], bvb = ((const float4*)bvv)[2 * j + 1];
        float o[8];
        o[0] = a[0] * inv + ska.x; o[1] = a[1] * inv + ska.y;
        o[2] = a[2] * inv + ska.z; o[3] = a[3] * inv + ska.w;
        o[4] = a[4] * inv + skb.x; o[5] = a[5] * inv + skb.y;
        o[6] = a[6] * inv + skb.z; o[7] = a[7] * inv + skb.w;
        o[0] = fmaxf((o[0] - bma.x) * rsqrtf(bva.x + EPSV) * bga.x + bba.x, 0.f);
        o[1] = fmaxf((o[1] - bma.y) * rsqrtf(bva.y + EPSV) * bga.y + bba.y, 0.f);
        o[2] = fmaxf((o[2] - bma.z) * rsqrtf(bva.z + EPSV) * bga.z + bba.z, 0.f);
        o[3] = fmaxf((o[3] - bma.w) * rsqrtf(bva.w + EPSV) * bga.w + bba.w, 0.f);
        o[4] = fmaxf((o[4] - bmb.x) * rsqrtf(bvb.x + EPSV) * bgb.x + bbb.x, 0.f);
        o[5] = fmaxf((o[5] - bmb.y) * rsqrtf(bvb.y + EPSV) * bgb.y + bbb.y, 0.f);
        o[6] = fmaxf((o[6] - bmb.z) * rsqrtf(bvb.z + EPSV) * bgb.z + bbb.z, 0.f);
        o[7] = fmaxf((o[7] - bmb.w) * rsqrtf(bvb.w + EPSV) * bgb.w + bbb.w, 0.f);
        float4* xo = (float4*)(g_x + (size_t)node * 64);
        xo[2 * j]     = make_float4(o[0], o[1], o[2], o[3]);
        xo[2 * j + 1] = make_float4(o[4], o[5], o[6], o[7]);
    }
}

// ================= head GEMM (also re-zeros g_cnt for the next call) =================
__global__ void k_head(const float* __restrict__ Wh, const float* __restrict__ bh,
                       float* __restrict__ out) {
    __shared__ float xs[32 * 64];
    __shared__ float ws[64 * 32];
    int t = threadIdx.x;
    int gid = blockIdx.x * blockDim.x + t;
    if (gid < NN) g_cnt[gid] = 0;            // prep histogram for next call
    int node0 = blockIdx.x * 32;
    const float4* xsrc = (const float4*)(g_x + (size_t)node0 * 64);
    ((float4*)xs)[t]       = xsrc[t];
    ((float4*)xs)[t + 256] = xsrc[t + 256];
    ((float4*)ws)[t]       = ((const float4*)Wh)[t];
    ((float4*)ws)[t + 256] = ((const float4*)Wh)[t + 256];
    __syncthreads();
    int col = t & 31, nr = t >> 5;
    float a0, a1, a2, a3;
    a0 = a1 = a2 = a3 = bh[col];
#pragma unroll 8
    for (int kk = 0; kk < 64; kk++) {
        float w = ws[kk * 32 + col];
        a0 = fmaf(xs[nr * 64 + kk],        w, a0);
        a1 = fmaf(xs[(nr + 8) * 64 + kk],  w, a1);
        a2 = fmaf(xs[(nr + 16) * 64 + kk], w, a2);
        a3 = fmaf(xs[(nr + 24) * 64 + kk], w, a3);
    }
    out[(size_t)(node0 + nr) * 32 + col]      = a0;
    out[(size_t)(node0 + nr + 8) * 32 + col]  = a1;
    out[(size_t)(node0 + nr + 16) * 32 + col] = a2;
    out[(size_t)(node0 + nr + 24) * 32 + col] = a3;
}

// ================= launch =================
extern "C" void kernel_launch(void* const* d_in, const int* in_sizes, int n_in,
                              void* d_out, int out_size) {
    const float* x    = (const float*)d_in[0];
    const int*   ei   = (const int*)  d_in[1];
    const float* Wq   = (const float*)d_in[2];
    const float* bq   = (const float*)d_in[3];
    const float* Wk   = (const float*)d_in[4];
    const float* bk   = (const float*)d_in[5];
    const float* Wv   = (const float*)d_in[6];
    const float* bv   = (const float*)d_in[7];
    const float* Ws   = (const float*)d_in[8];
    const float* bs   = (const float*)d_in[9];
    const float* bn_g = (const float*)d_in[10];
    const float* bn_b = (const float*)d_in[11];
    const float* bn_m = (const float*)d_in[12];
    const float* bn_v = (const float*)d_in[13];
    const float* Wh   = (const float*)d_in[14];
    const float* bh   = (const float*)d_in[15];
    float* out = (float*)d_out;

    const int NB = (NN + 255) / 256;           // 391
    const int GA = (NN * 32 + 255) / 256;      // warp per node
    const int GH = NN / 32;                    // 3125

    uint4* wf_base;
    cudaGetSymbolAddress((void**)&wf_base, g_wf);

    k_prep1<<<EB + WPREPB, 256>>>(ei, Wq, Wk, Wv, Ws);            // 1: hist + wprep
    k_scan1<<<SBLK, 1024>>>();                                     // 2
    k_scan_fix<<<NB, 256>>>();                                     // 3
    k_gemm_scatter<<<GR + EB, 256>>>(x, wf_base,                   // 4: gemm L0 + scatter (profiled)
                                     bq, bk, bv, bs, ei);
    k_attn<<<GA, 256>>>(bn_g, bn_b, bn_m, bn_v);                   // 5

    for (int l = 1; l < 3; l++) {
        size_t bo = (size_t)l * HID;
        k_gemm_fused<<<GR, 256>>>(wf_base + (size_t)l * 4096,
                                  bq + bo, bk + bo, bv + bo, bs + bo);
        k_attn<<<GA, 256>>>(bn_g + bo, bn_b + bo, bn_m + bo, bn_v + bo);
    }
    k_head<<<GH, 256>>>(Wh, bh, out);
}

// round 12
// speedup vs baseline: 1.0518x; 1.0140x over previous
#include <cuda_runtime.h>
#include <cuda_fp16.h>
#include <cuda_bf16.h>
#include <cstdint>

#define NN 100000
#define EE 1600000
#define HID 64
#define OC 32
#define EPSV 1e-5f
#define EB 6250          // hist/scatter blocks (EE/256)
#define WPREPB 48        // wprep blocks (3*4096/256)
#define SBLK 98          // scan blocks ((NN+1023)/1024)
#define GR2 782          // gemm blocks: 4 tiles of 32 rows each (782*128 >= NN)

// ---------------- scratch (device globals; zero-initialized at module load) ----------------
__device__ __half g_qh[(size_t)NN * HID];    // q in fp16 (128 B/node)
__device__ float  g_skip[(size_t)NN * HID];
__device__ float  g_x[(size_t)NN * HID];
__device__ __half g_kvh[(size_t)NN * 128];   // per node: k[64] halves then v[64] halves (256 B)
__device__ uint4  g_wf[3 * 4096];            // per layer: 4 sel x 4 kt x 8 nt x 32 lanes {bh0,bh1,bl0,bl1}

__device__ int g_cnt[NN];                    // zeroed by k_head at end of every call
__device__ int g_rowstart[NN + 1];
__device__ int g_cursor[NN];
__device__ int g_csrsrc[EE];
__device__ int g_bsum[128];

// ================= GEMM helpers =================
__device__ __forceinline__ void mma_bf16(float* c, uint32_t a0, uint32_t a1,
                                         uint32_t a2, uint32_t a3,
                                         uint32_t b0, uint32_t b1) {
    asm volatile("mma.sync.aligned.m16n8k16.row.col.f32.bf16.bf16.f32 "
                 "{%0,%1,%2,%3}, {%4,%5,%6,%7}, {%8,%9}, {%0,%1,%2,%3};"
                 : "+f"(c[0]), "+f"(c[1]), "+f"(c[2]), "+f"(c[3])
                 : "r"(a0), "r"(a1), "r"(a2), "r"(a3), "r"(b0), "r"(b1));
}
__device__ __forceinline__ uint32_t pack_hi(float a, float b) {
    __nv_bfloat162 h = __floats2bfloat162_rn(a, b);
    return *(uint32_t*)&h;
}
__device__ __forceinline__ uint32_t pack_lo(float a, float b, uint32_t hi) {
    __nv_bfloat162 h = *(__nv_bfloat162*)&hi;
    __nv_bfloat162 l = __floats2bfloat162_rn(a - __bfloat162float(h.x),
                                             b - __bfloat162float(h.y));
    return *(uint32_t*)&l;
}

#define XSTR 72   // bf16 row stride: conflict-free

// gemm body: computes 32 rows starting at row0 for all 4 output matrices.
__device__ __forceinline__ void gemm_body(
        const float* __restrict__ x, const uint4* __restrict__ wf, int row0,
        const float* __restrict__ bq, const float* __restrict__ bk,
        const float* __restrict__ bv, const float* __restrict__ bs,
        __nv_bfloat16* xh, __nv_bfloat16* xl) {
    int t = threadIdx.x;
#pragma unroll
    for (int i = 0; i < 2; i++) {
        int idx = t + 256 * i;
        int r = idx >> 4, c4 = idx & 15;
        float4 val = ((const float4*)(x + (size_t)(row0 + r) * 64))[c4];
        uint32_t h01 = pack_hi(val.x, val.y);
        uint32_t h23 = pack_hi(val.z, val.w);
        uint32_t l01 = pack_lo(val.x, val.y, h01);
        uint32_t l23 = pack_lo(val.z, val.w, h23);
        *(uint2*)(&xh[r * XSTR + c4 * 4]) = make_uint2(h01, h23);
        *(uint2*)(&xl[r * XSTR + c4 * 4]) = make_uint2(l01, l23);
    }
    __syncthreads();

    int wid = t >> 5, lane = t & 31;
    int tig = lane & 3, grp = lane >> 2;
    int cloc = wid * 8 + 2 * tig;

    float acc[4][2][4];
    {
        const float* biases[4] = {bq, bk, bv, bs};
#pragma unroll
        for (int sel = 0; sel < 4; sel++) {
            float b0 = biases[sel][cloc], b1 = biases[sel][cloc + 1];
#pragma unroll
            for (int mt = 0; mt < 2; mt++) {
                acc[sel][mt][0] = b0; acc[sel][mt][1] = b1;
                acc[sel][mt][2] = b0; acc[sel][mt][3] = b1;
            }
        }
    }

#pragma unroll
    for (int kt = 0; kt < 4; kt++) {
        uint4 bf[4];
#pragma unroll
        for (int sel = 0; sel < 4; sel++)
            bf[sel] = wf[((sel * 4 + kt) * 8 + wid) * 32 + lane];
        int k = kt * 16 + tig * 2;
#pragma unroll
        for (int mt = 0; mt < 2; mt++) {
            int r = mt * 16 + grp;
            uint32_t h0 = *(uint32_t*)&xh[r * XSTR + k];
            uint32_t h1 = *(uint32_t*)&xh[(r + 8) * XSTR + k];
            uint32_t h2 = *(uint32_t*)&xh[r * XSTR + k + 8];
            uint32_t h3 = *(uint32_t*)&xh[(r + 8) * XSTR + k + 8];
            uint32_t l0 = *(uint32_t*)&xl[r * XSTR + k];
            uint32_t l1 = *(uint32_t*)&xl[(r + 8) * XSTR + k];
            uint32_t l2 = *(uint32_t*)&xl[r * XSTR + k + 8];
            uint32_t l3 = *(uint32_t*)&xl[(r + 8) * XSTR + k + 8];
#pragma unroll
            for (int sel = 0; sel < 4; sel++) {
                mma_bf16(acc[sel][mt], h0, h1, h2, h3, bf[sel].x, bf[sel].y);
                mma_bf16(acc[sel][mt], h0, h1, h2, h3, bf[sel].z, bf[sel].w);
                mma_bf16(acc[sel][mt], l0, l1, l2, l3, bf[sel].x, bf[sel].y);
            }
        }
    }

#pragma unroll
    for (int sel = 0; sel < 4; sel++) {
#pragma unroll
        for (int mt = 0; mt < 2; mt++) {
            int r0g = row0 + mt * 16 + grp;
            int r1g = r0g + 8;
            float* a = acc[sel][mt];
            if (sel == 0) {
                *(__half2*)(g_qh + (size_t)r0g * 64 + cloc) = __floats2half2_rn(a[0], a[1]);
                *(__half2*)(g_qh + (size_t)r1g * 64 + cloc) = __floats2half2_rn(a[2], a[3]);
            } else if (sel == 3) {
                *(float2*)(g_skip + (size_t)r0g * 64 + cloc) = make_float2(a[0], a[1]);
                *(float2*)(g_skip + (size_t)r1g * 64 + cloc) = make_float2(a[2], a[3]);
            } else {
                int off = (sel == 2) ? 64 : 0;
                *(__half2*)(g_kvh + (size_t)r0g * 128 + off + cloc) = __floats2half2_rn(a[0], a[1]);
                *(__half2*)(g_kvh + (size_t)r1g * 128 + off + cloc) = __floats2half2_rn(a[2], a[3]);
            }
        }
    }
}

// ================= launch 1: hist + W-frag prep (disjoint block ranges) =================
__global__ void k_prep1(const int* __restrict__ ei,
                        const float* __restrict__ Wq, const float* __restrict__ Wk,
                        const float* __restrict__ Wv, const float* __restrict__ Ws) {
    int b = blockIdx.x;
    if (b < EB) {
        int e = b * 256 + threadIdx.x;
        if (e < EE) atomicAdd(&g_cnt[ei[EE + e]], 1);
        return;
    }
    int t = (b - EB) * 256 + threadIdx.x;
    if (t >= 3 * 4096) return;
    int lane  = t & 31;
    int nt    = (t >> 5) & 7;
    int kt    = (t >> 8) & 3;
    int sel   = (t >> 10) & 3;
    int layer = t >> 12;
    const float* Wb = (sel == 0) ? Wq : (sel == 1) ? Wk : (sel == 2) ? Wv : Ws;
    const float* W = Wb + (size_t)layer * HID * HID;
    int grp = lane >> 2, tig = lane & 3;
    int n  = nt * 8 + grp;
    int k0 = kt * 16 + tig * 2;
    float b00 = W[k0 * 64 + n],       b01 = W[(k0 + 1) * 64 + n];
    float b10 = W[(k0 + 8) * 64 + n], b11 = W[(k0 + 9) * 64 + n];
    uint32_t h0 = pack_hi(b00, b01), h1 = pack_hi(b10, b11);
    uint32_t l0 = pack_lo(b00, b01, h0), l1 = pack_lo(b10, b11, h1);
    uint4 o; o.x = h0; o.y = h1; o.z = l0; o.w = l1;
    g_wf[t] = o;
}

// ================= launch 2: scan stage 1 =================
__global__ void k_scan1() {
    __shared__ int sh[1024];
    int i = blockIdx.x * 1024 + threadIdx.x;
    int v = (i < NN) ? g_cnt[i] : 0;
    sh[threadIdx.x] = v;
    __syncthreads();
    for (int off = 1; off < 1024; off <<= 1) {
        int t = (threadIdx.x >= off) ? sh[threadIdx.x - off] : 0;
        __syncthreads();
        sh[threadIdx.x] += t;
        __syncthreads();
    }
    if (i < NN) g_rowstart[i] = sh[threadIdx.x] - v;
    if (threadIdx.x == 1023) g_bsum[blockIdx.x] = sh[1023];
}

// ================= launch 3: scan fixup =================
__global__ void k_scan_fix() {
    __shared__ int sh[128];
    int t = threadIdx.x;
    if (t < 128) sh[t] = (t < SBLK) ? g_bsum[t] : 0;
    __syncthreads();
    for (int off = 1; off < 128; off <<= 1) {
        int u = (t < 128 && t >= off) ? sh[t - off] : 0;
        __syncthreads();
        if (t < 128) sh[t] += u;
        __syncthreads();
    }
    __shared__ int pre[128];
    if (t < 128) pre[t] = sh[t] - ((t < SBLK) ? g_bsum[t] : 0);
    __syncthreads();
    int i = blockIdx.x * blockDim.x + t;
    if (i < NN) {
        int rs = g_rowstart[i] + pre[i >> 10];
        g_rowstart[i] = rs;
        g_cursor[i] = rs;
    }
    if (i == 0) g_rowstart[NN] = EE;
}

// ================= launch 4: gemm (4 x 32-row tiles per block; wf L1-resident) =================
__global__ void __launch_bounds__(256, 2) k_gemm_fused(
        const float* __restrict__ xin, const uint4* __restrict__ wf,
        const float* __restrict__ bq, const float* __restrict__ bk,
        const float* __restrict__ bv, const float* __restrict__ bs) {
    __shared__ __nv_bfloat16 xh[32 * XSTR];
    __shared__ __nv_bfloat16 xl[32 * XSTR];
    const float* x = xin ? xin : g_x;
#pragma unroll
    for (int it = 0; it < 4; it++) {
        int row0 = blockIdx.x * 128 + it * 32;
        if (row0 >= NN) break;
        if (it) __syncthreads();    // smem reuse across tiles
        gemm_body(x, wf, row0, bq, bk, bv, bs, xh, xl);
    }
}

// ================= launch 5: scatter (standalone, high occupancy) =================
__global__ void k_scatter(const int* __restrict__ ei) {
    int e = blockIdx.x * blockDim.x + threadIdx.x;
    if (e >= EE) return;
    int s = ei[e], d = ei[EE + e];
    int pos = atomicAdd(&g_cursor[d], 1);
    g_csrsrc[pos] = s;
}

// ================= fused attention: 16-edge batches + index prefetch =================
__device__ __forceinline__ float dot8(const float4& qa, const float4& qb, const uint4& kk) {
    float2 k0 = __half22float2(*(__half2*)&kk.x);
    float2 k1 = __half22float2(*(__half2*)&kk.y);
    float2 k2 = __half22float2(*(__half2*)&kk.z);
    float2 k3 = __half22float2(*(__half2*)&kk.w);
    return qa.x * k0.x + qa.y * k0.y + qa.z * k1.x + qa.w * k1.y
         + qb.x * k2.x + qb.y * k2.y + qb.z * k3.x + qb.w * k3.y;
}
__device__ __forceinline__ void acc8(float* a, float ex, const uint4& vv) {
    float2 v0 = __half22float2(*(__half2*)&vv.x);
    float2 v1 = __half22float2(*(__half2*)&vv.y);
    float2 v2 = __half22float2(*(__half2*)&vv.z);
    float2 v3 = __half22float2(*(__half2*)&vv.w);
    a[0] = fmaf(ex, v0.x, a[0]); a[1] = fmaf(ex, v0.y, a[1]);
    a[2] = fmaf(ex, v1.x, a[2]); a[3] = fmaf(ex, v1.y, a[3]);
    a[4] = fmaf(ex, v2.x, a[4]); a[5] = fmaf(ex, v2.y, a[5]);
    a[6] = fmaf(ex, v3.x, a[6]); a[7] = fmaf(ex, v3.y, a[7]);
}

__global__ void k_attn(const float* __restrict__ bg, const float* __restrict__ bb,
                       const float* __restrict__ bm, const float* __restrict__ bvv) {
    int warp = (blockIdx.x * blockDim.x + threadIdx.x) >> 5;
    if (warp >= NN) return;
    int lane = threadIdx.x & 31;
    int g = lane >> 3, j = lane & 7;
    int node = warp;

    uint4 qq = ((const uint4*)(g_qh + (size_t)node * 64))[j];
    float2 q0 = __half22float2(*(__half2*)&qq.x);
    float2 q1 = __half22float2(*(__half2*)&qq.y);
    float2 q2 = __half22float2(*(__half2*)&qq.z);
    float2 q3 = __half22float2(*(__half2*)&qq.w);
    float4 qa = make_float4(q0.x, q0.y, q1.x, q1.y);
    float4 qb = make_float4(q2.x, q2.y, q3.x, q3.y);

    int beg = g_rowstart[node];
    int end = g_rowstart[node + 1];

    float a[8] = {0.f, 0.f, 0.f, 0.f, 0.f, 0.f, 0.f, 0.f};
    float den = 0.f;

    if (beg < end) {
        int lim = end - 1;
        int nA = g_csrsrc[min(beg + g, lim)];
        int nB = g_csrsrc[min(beg + 4 + g, lim)];
        int nC = g_csrsrc[min(beg + 8 + g, lim)];
        int nD = g_csrsrc[min(beg + 12 + g, lim)];
        for (int i = beg; i < end; i += 16) {
            int sA = nA, sB = nB, sC = nC, sD = nD;
            int ni = i + 16;
            nA = g_csrsrc[min(ni + g, lim)];
            nB = g_csrsrc[min(ni + 4 + g, lim)];
            nC = g_csrsrc[min(ni + 8 + g, lim)];
            nD = g_csrsrc[min(ni + 12 + g, lim)];

            const uint4* kvA = (const uint4*)(g_kvh + (size_t)sA * 128);
            const uint4* kvB = (const uint4*)(g_kvh + (size_t)sB * 128);
            const uint4* kvC = (const uint4*)(g_kvh + (size_t)sC * 128);
            const uint4* kvD = (const uint4*)(g_kvh + (size_t)sD * 128);
            uint4 kA = kvA[j], kB = kvB[j], kC = kvC[j], kD = kvD[j];
            uint4 vA = kvA[8 + j], vB = kvB[8 + j], vC = kvC[8 + j], vD = kvD[8 + j];

            float pA = dot8(qa, qb, kA);
            float pB = dot8(qa, qb, kB);
            float pC = dot8(qa, qb, kC);
            float pD = dot8(qa, qb, kD);
            pA += __shfl_xor_sync(0xffffffffu, pA, 1);
            pB += __shfl_xor_sync(0xffffffffu, pB, 1);
            pC += __shfl_xor_sync(0xffffffffu, pC, 1);
            pD += __shfl_xor_sync(0xffffffffu, pD, 1);
            float eA = (i + g < end)      ? __expf(pA * 0.25f) : 0.f;
            float eB = (i + 4 + g < end)  ? __expf(pB * 0.25f) : 0.f;
            float eC = (i + 8 + g < end)  ? __expf(pC * 0.25f) : 0.f;
            float eD = (i + 12 + g < end) ? __expf(pD * 0.25f) : 0.f;
            acc8(a, eA, vA);
            acc8(a, eB, vB);
            acc8(a, eC, vC);
            acc8(a, eD, vD);
            den += (eA + eB) + (eC + eD);
        }
    }

#pragma unroll
    for (int c = 0; c < 8; c++) {
        a[c] += __shfl_xor_sync(0xffffffffu, a[c], 8);
        a[c] += __shfl_xor_sync(0xffffffffu, a[c], 16);
    }
    den += __shfl_xor_sync(0xffffffffu, den, 8);
    den += __shfl_xor_sync(0xffffffffu, den, 16);

    if (g == 0) {
        float inv = (den > 0.f) ? __frcp_rn(den) : 0.f;
        float4 ska = ((const float4*)(g_skip + (size_t)node * 64))[2 * j];
        float4 skb = ((const float4*)(g_skip + (size_t)node * 64))[2 * j + 1];
        float4 bga = ((const float4*)bg)[2 * j],  bgb = ((const float4*)bg)[2 * j + 1];
        float4 bba = ((const float4*)bb)[2 * j],  bbb = ((const float4*)bb)[2 * j + 1];
        float4 bma = ((const float4*)bm)[2 * j],  bmb = ((const float4*)bm)[2 * j + 1];
        float4 bva = ((const float4*)bvv)[2 * j], bvb = ((const float4*)bvv)[2 * j + 1];
        float o[8];
        o[0] = a[0] * inv + ska.x; o[1] = a[1] * inv + ska.y;
        o[2] = a[2] * inv + ska.z; o[3] = a[3] * inv + ska.w;
        o[4] = a[4] * inv + skb.x; o[5] = a[5] * inv + skb.y;
        o[6] = a[6] * inv + skb.z; o[7] = a[7] * inv + skb.w;
        o[0] = fmaxf((o[0] - bma.x) * rsqrtf(bva.x + EPSV) * bga.x + bba.x, 0.f);
        o[1] = fmaxf((o[1] - bma.y) * rsqrtf(bva.y + EPSV) * bga.y + bba.y, 0.f);
        o[2] = fmaxf((o[2] - bma.z) * rsqrtf(bva.z + EPSV) * bga.z + bba.z, 0.f);
        o[3] = fmaxf((o[3] - bma.w) * rsqrtf(bva.w + EPSV) * bga.w + bba.w, 0.f);
        o[4] = fmaxf((o[4] - bmb.x) * rsqrtf(bvb.x + EPSV) * bgb.x + bbb.x, 0.f);
        o[5] = fmaxf((o[5] - bmb.y) * rsqrtf(bvb.y + EPSV) * bgb.y + bbb.y, 0.f);
        o[6] = fmaxf((o[6] - bmb.z) * rsqrtf(bvb.z + EPSV) * bgb.z + bbb.z, 0.f);
        o[7] = fmaxf((o[7] - bmb.w) * rsqrtf(bvb.w + EPSV) * bgb.w + bbb.w, 0.f);
        float4* xo = (float4*)(g_x + (size_t)node * 64);
        xo[2 * j]     = make_float4(o[0], o[1], o[2], o[3]);
        xo[2 * j + 1] = make_float4(o[4], o[5], o[6], o[7]);
    }
}

// ================= head GEMM (also re-zeros g_cnt for the next call) =================
__global__ void k_head(const float* __restrict__ Wh, const float* __restrict__ bh,
                       float* __restrict__ out) {
    __shared__ float xs[32 * 64];
    __shared__ float ws[64 * 32];
    int t = threadIdx.x;
    int gid = blockIdx.x * blockDim.x + t;
    if (gid < NN) g_cnt[gid] = 0;            // prep histogram for next call
    int node0 = blockIdx.x * 32;
    const float4* xsrc = (const float4*)(g_x + (size_t)node0 * 64);
    ((float4*)xs)[t]       = xsrc[t];
    ((float4*)xs)[t + 256] = xsrc[t + 256];
    ((float4*)ws)[t]       = ((const float4*)Wh)[t];
    ((float4*)ws)[t + 256] = ((const float4*)Wh)[t + 256];
    __syncthreads();
    int col = t & 31, nr = t >> 5;
    float a0, a1, a2, a3;
    a0 = a1 = a2 = a3 = bh[col];
#pragma unroll 8
    for (int kk = 0; kk < 64; kk++) {
        float w = ws[kk * 32 + col];
        a0 = fmaf(xs[nr * 64 + kk],        w, a0);
        a1 = fmaf(xs[(nr + 8) * 64 + kk],  w, a1);
        a2 = fmaf(xs[(nr + 16) * 64 + kk], w, a2);
        a3 = fmaf(xs[(nr + 24) * 64 + kk], w, a3);
    }
    out[(size_t)(node0 + nr) * 32 + col]      = a0;
    out[(size_t)(node0 + nr + 8) * 32 + col]  = a1;
    out[(size_t)(node0 + nr + 16) * 32 + col] = a2;
    out[(size_t)(node0 + nr + 24) * 32 + col] = a3;
}

// ================= launch =================
extern "C" void kernel_launch(void* const* d_in, const int* in_sizes, int n_in,
                              void* d_out, int out_size) {
    const float* x    = (const float*)d_in[0];
    const int*   ei   = (const int*)  d_in[1];
    const float* Wq   = (const float*)d_in[2];
    const float* bq   = (const float*)d_in[3];
    const float* Wk   = (const float*)d_in[4];
    const float* bk   = (const float*)d_in[5];
    const float* Wv   = (const float*)d_in[6];
    const float* bv   = (const float*)d_in[7];
    const float* Ws   = (const float*)d_in[8];
    const float* bs   = (const float*)d_in[9];
    const float* bn_g = (const float*)d_in[10];
    const float* bn_b = (const float*)d_in[11];
    const float* bn_m = (const float*)d_in[12];
    const float* bn_v = (const float*)d_in[13];
    const float* Wh   = (const float*)d_in[14];
    const float* bh   = (const float*)d_in[15];
    float* out = (float*)d_out;

    const int NB = (NN + 255) / 256;           // 391
    const int GA = (NN * 32 + 255) / 256;      // warp per node
    const int GH = NN / 32;                    // 3125

    uint4* wf_base;
    cudaGetSymbolAddress((void**)&wf_base, g_wf);

    k_prep1<<<EB + WPREPB, 256>>>(ei, Wq, Wk, Wv, Ws);            // 1: hist + wprep
    k_scan1<<<SBLK, 1024>>>();                                     // 2
    k_scan_fix<<<NB, 256>>>();                                     // 3
    k_gemm_fused<<<GR2, 256>>>(x, wf_base, bq, bk, bv, bs);        // 4: gemm L0 (profiled)
    k_scatter<<<EB, 256>>>(ei);                                    // 5
    k_attn<<<GA, 256>>>(bn_g, bn_b, bn_m, bn_v);                   // 6

    for (int l = 1; l < 3; l++) {
        size_t bo = (size_t)l * HID;
        k_gemm_fused<<<GR2, 256>>>(nullptr, wf_base + (size_t)l * 4096,
                                   bq + bo, bk + bo, bv + bo, bs + bo);
        k_attn<<<GA, 256>>>(bn_g + bo, bn_b + bo, bn_m + bo, bn_v + bo);
    }
    k_head<<<GH, 256>>>(Wh, bh, out);
}

// round 13
// speedup vs baseline: 1.0520x; 1.0002x over previous
#include <cuda_runtime.h>
#include <cuda_fp16.h>
#include <cuda_bf16.h>
#include <cstdint>

#define NN 100000
#define EE 1600000
#define HID 64
#define OC 32
#define EPSV 1e-5f
#define EB 6250          // hist/scatter blocks (EE/256)
#define WPREPB 48        // wprep blocks (3*4096/256)
#define SBLK 98          // scan blocks ((NN+1023)/1024)
#define GR2 782          // gemm blocks: 4 tiles of 32 rows each (782*128 >= NN)

// ---------------- scratch (device globals; zero-initialized at module load) ----------------
__device__ __half g_qh[(size_t)NN * HID];    // q in fp16 (128 B/node)
__device__ float  g_skip[(size_t)NN * HID];
__device__ float  g_x[(size_t)NN * HID];
__device__ __half g_kvh[(size_t)NN * 128];   // per node: k[64] halves then v[64] halves (256 B)
__device__ uint4  g_wf[3 * 4096];            // per layer: 4 sel x 4 kt x 8 nt x 32 lanes {bh0,bh1,bl0,bl1}

__device__ int g_cnt[NN];                    // zeroed by k_head at end of every call
__device__ int g_rowstart[NN + 1];
__device__ int g_cursor[NN];
__device__ int g_csrsrc[EE];
__device__ int g_bsum[128];

// ================= GEMM helpers =================
__device__ __forceinline__ void mma_bf16(float* c, uint32_t a0, uint32_t a1,
                                         uint32_t a2, uint32_t a3,
                                         uint32_t b0, uint32_t b1) {
    asm volatile("mma.sync.aligned.m16n8k16.row.col.f32.bf16.bf16.f32 "
                 "{%0,%1,%2,%3}, {%4,%5,%6,%7}, {%8,%9}, {%0,%1,%2,%3};"
                 : "+f"(c[0]), "+f"(c[1]), "+f"(c[2]), "+f"(c[3])
                 : "r"(a0), "r"(a1), "r"(a2), "r"(a3), "r"(b0), "r"(b1));
}
__device__ __forceinline__ uint32_t pack_hi(float a, float b) {
    __nv_bfloat162 h = __floats2bfloat162_rn(a, b);
    return *(uint32_t*)&h;
}
__device__ __forceinline__ uint32_t pack_lo(float a, float b, uint32_t hi) {
    __nv_bfloat162 h = *(__nv_bfloat162*)&hi;
    __nv_bfloat162 l = __floats2bfloat162_rn(a - __bfloat162float(h.x),
                                             b - __bfloat162float(h.y));
    return *(uint32_t*)&l;
}

#define XSTR 72   // bf16 row stride: conflict-free

// gemm body: computes 32 rows starting at row0 for all 4 output matrices.
// kt loop deliberately NOT unrolled: keeps only one kt's wf fragments live
// (16 regs instead of 64) so the kernel fits 3 CTAs/SM.
__device__ __forceinline__ void gemm_body(
        const float* __restrict__ x, const uint4* __restrict__ wf, int row0,
        const float* __restrict__ bq, const float* __restrict__ bk,
        const float* __restrict__ bv, const float* __restrict__ bs,
        __nv_bfloat16* xh, __nv_bfloat16* xl) {
    int t = threadIdx.x;
#pragma unroll
    for (int i = 0; i < 2; i++) {
        int idx = t + 256 * i;
        int r = idx >> 4, c4 = idx & 15;
        float4 val = ((const float4*)(x + (size_t)(row0 + r) * 64))[c4];
        uint32_t h01 = pack_hi(val.x, val.y);
        uint32_t h23 = pack_hi(val.z, val.w);
        uint32_t l01 = pack_lo(val.x, val.y, h01);
        uint32_t l23 = pack_lo(val.z, val.w, h23);
        *(uint2*)(&xh[r * XSTR + c4 * 4]) = make_uint2(h01, h23);
        *(uint2*)(&xl[r * XSTR + c4 * 4]) = make_uint2(l01, l23);
    }
    __syncthreads();

    int wid = t >> 5, lane = t & 31;
    int tig = lane & 3, grp = lane >> 2;
    int cloc = wid * 8 + 2 * tig;

    float acc[4][2][4];
    {
        const float* biases[4] = {bq, bk, bv, bs};
#pragma unroll
        for (int sel = 0; sel < 4; sel++) {
            float b0 = biases[sel][cloc], b1 = biases[sel][cloc + 1];
#pragma unroll
            for (int mt = 0; mt < 2; mt++) {
                acc[sel][mt][0] = b0; acc[sel][mt][1] = b1;
                acc[sel][mt][2] = b0; acc[sel][mt][3] = b1;
            }
        }
    }

#pragma unroll 1
    for (int kt = 0; kt < 4; kt++) {
        uint4 bf[4];
#pragma unroll
        for (int sel = 0; sel < 4; sel++)
            bf[sel] = wf[((sel * 4 + kt) * 8 + wid) * 32 + lane];
        int k = kt * 16 + tig * 2;
#pragma unroll
        for (int mt = 0; mt < 2; mt++) {
            int r = mt * 16 + grp;
            uint32_t h0 = *(uint32_t*)&xh[r * XSTR + k];
            uint32_t h1 = *(uint32_t*)&xh[(r + 8) * XSTR + k];
            uint32_t h2 = *(uint32_t*)&xh[r * XSTR + k + 8];
            uint32_t h3 = *(uint32_t*)&xh[(r + 8) * XSTR + k + 8];
            uint32_t l0 = *(uint32_t*)&xl[r * XSTR + k];
            uint32_t l1 = *(uint32_t*)&xl[(r + 8) * XSTR + k];
            uint32_t l2 = *(uint32_t*)&xl[r * XSTR + k + 8];
            uint32_t l3 = *(uint32_t*)&xl[(r + 8) * XSTR + k + 8];
#pragma unroll
            for (int sel = 0; sel < 4; sel++) {
                mma_bf16(acc[sel][mt], h0, h1, h2, h3, bf[sel].x, bf[sel].y);
                mma_bf16(acc[sel][mt], h0, h1, h2, h3, bf[sel].z, bf[sel].w);
                mma_bf16(acc[sel][mt], l0, l1, l2, l3, bf[sel].x, bf[sel].y);
            }
        }
    }

#pragma unroll
    for (int sel = 0; sel < 4; sel++) {
#pragma unroll
        for (int mt = 0; mt < 2; mt++) {
            int r0g = row0 + mt * 16 + grp;
            int r1g = r0g + 8;
            float* a = acc[sel][mt];
            if (sel == 0) {
                *(__half2*)(g_qh + (size_t)r0g * 64 + cloc) = __floats2half2_rn(a[0], a[1]);
                *(__half2*)(g_qh + (size_t)r1g * 64 + cloc) = __floats2half2_rn(a[2], a[3]);
            } else if (sel == 3) {
                *(float2*)(g_skip + (size_t)r0g * 64 + cloc) = make_float2(a[0], a[1]);
                *(float2*)(g_skip + (size_t)r1g * 64 + cloc) = make_float2(a[2], a[3]);
            } else {
                int off = (sel == 2) ? 64 : 0;
                *(__half2*)(g_kvh + (size_t)r0g * 128 + off + cloc) = __floats2half2_rn(a[0], a[1]);
                *(__half2*)(g_kvh + (size_t)r1g * 128 + off + cloc) = __floats2half2_rn(a[2], a[3]);
            }
        }
    }
}

// ================= launch 1: hist + W-frag prep (disjoint block ranges) =================
__global__ void k_prep1(const int* __restrict__ ei,
                        const float* __restrict__ Wq, const float* __restrict__ Wk,
                        const float* __restrict__ Wv, const float* __restrict__ Ws) {
    int b = blockIdx.x;
    if (b < EB) {
        int e = b * 256 + threadIdx.x;
        if (e < EE) atomicAdd(&g_cnt[ei[EE + e]], 1);
        return;
    }
    int t = (b - EB) * 256 + threadIdx.x;
    if (t >= 3 * 4096) return;
    int lane  = t & 31;
    int nt    = (t >> 5) & 7;
    int kt    = (t >> 8) & 3;
    int sel   = (t >> 10) & 3;
    int layer = t >> 12;
    const float* Wb = (sel == 0) ? Wq : (sel == 1) ? Wk : (sel == 2) ? Wv : Ws;
    const float* W = Wb + (size_t)layer * HID * HID;
    int grp = lane >> 2, tig = lane & 3;
    int n  = nt * 8 + grp;
    int k0 = kt * 16 + tig * 2;
    float b00 = W[k0 * 64 + n],       b01 = W[(k0 + 1) * 64 + n];
    float b10 = W[(k0 + 8) * 64 + n], b11 = W[(k0 + 9) * 64 + n];
    uint32_t h0 = pack_hi(b00, b01), h1 = pack_hi(b10, b11);
    uint32_t l0 = pack_lo(b00, b01, h0), l1 = pack_lo(b10, b11, h1);
    uint4 o; o.x = h0; o.y = h1; o.z = l0; o.w = l1;
    g_wf[t] = o;
}

// ================= launch 2: scan stage 1 =================
__global__ void k_scan1() {
    __shared__ int sh[1024];
    int i = blockIdx.x * 1024 + threadIdx.x;
    int v = (i < NN) ? g_cnt[i] : 0;
    sh[threadIdx.x] = v;
    __syncthreads();
    for (int off = 1; off < 1024; off <<= 1) {
        int t = (threadIdx.x >= off) ? sh[threadIdx.x - off] : 0;
        __syncthreads();
        sh[threadIdx.x] += t;
        __syncthreads();
    }
    if (i < NN) g_rowstart[i] = sh[threadIdx.x] - v;
    if (threadIdx.x == 1023) g_bsum[blockIdx.x] = sh[1023];
}

// ================= launch 3: scan fixup =================
__global__ void k_scan_fix() {
    __shared__ int sh[128];
    int t = threadIdx.x;
    if (t < 128) sh[t] = (t < SBLK) ? g_bsum[t] : 0;
    __syncthreads();
    for (int off = 1; off < 128; off <<= 1) {
        int u = (t < 128 && t >= off) ? sh[t - off] : 0;
        __syncthreads();
        if (t < 128) sh[t] += u;
        __syncthreads();
    }
    __shared__ int pre[128];
    if (t < 128) pre[t] = sh[t] - ((t < SBLK) ? g_bsum[t] : 0);
    __syncthreads();
    int i = blockIdx.x * blockDim.x + t;
    if (i < NN) {
        int rs = g_rowstart[i] + pre[i >> 10];
        g_rowstart[i] = rs;
        g_cursor[i] = rs;
    }
    if (i == 0) g_rowstart[NN] = EE;
}

// ================= launch 4: gemm (4 x 32-row tiles per block; 3 CTAs/SM) =================
__global__ void __launch_bounds__(256, 3) k_gemm_fused(
        const float* __restrict__ xin, const uint4* __restrict__ wf,
        const float* __restrict__ bq, const float* __restrict__ bk,
        const float* __restrict__ bv, const float* __restrict__ bs) {
    __shared__ __nv_bfloat16 xh[32 * XSTR];
    __shared__ __nv_bfloat16 xl[32 * XSTR];
    const float* x = xin ? xin : g_x;
#pragma unroll 1
    for (int it = 0; it < 4; it++) {
        int row0 = blockIdx.x * 128 + it * 32;
        if (row0 >= NN) break;
        if (it) __syncthreads();    // smem reuse across tiles
        gemm_body(x, wf, row0, bq, bk, bv, bs, xh, xl);
    }
}

// ================= launch 5: scatter (standalone, high occupancy) =================
__global__ void k_scatter(const int* __restrict__ ei) {
    int e = blockIdx.x * blockDim.x + threadIdx.x;
    if (e >= EE) return;
    int s = ei[e], d = ei[EE + e];
    int pos = atomicAdd(&g_cursor[d], 1);
    g_csrsrc[pos] = s;
}

// ================= fused attention: 16-edge batches + index prefetch =================
__device__ __forceinline__ float dot8(const float4& qa, const float4& qb, const uint4& kk) {
    float2 k0 = __half22float2(*(__half2*)&kk.x);
    float2 k1 = __half22float2(*(__half2*)&kk.y);
    float2 k2 = __half22float2(*(__half2*)&kk.z);
    float2 k3 = __half22float2(*(__half2*)&kk.w);
    return qa.x * k0.x + qa.y * k0.y + qa.z * k1.x + qa.w * k1.y
         + qb.x * k2.x + qb.y * k2.y + qb.z * k3.x + qb.w * k3.y;
}
__device__ __forceinline__ void acc8(float* a, float ex, const uint4& vv) {
    float2 v0 = __half22float2(*(__half2*)&vv.x);
    float2 v1 = __half22float2(*(__half2*)&vv.y);
    float2 v2 = __half22float2(*(__half2*)&vv.z);
    float2 v3 = __half22float2(*(__half2*)&vv.w);
    a[0] = fmaf(ex, v0.x, a[0]); a[1] = fmaf(ex, v0.y, a[1]);
    a[2] = fmaf(ex, v1.x, a[2]); a[3] = fmaf(ex, v1.y, a[3]);
    a[4] = fmaf(ex, v2.x, a[4]); a[5] = fmaf(ex, v2.y, a[5]);
    a[6] = fmaf(ex, v3.x, a[6]); a[7] = fmaf(ex, v3.y, a[7]);
}

__global__ void k_attn(const float* __restrict__ bg, const float* __restrict__ bb,
                       const float* __restrict__ bm, const float* __restrict__ bvv) {
    int warp = (blockIdx.x * blockDim.x + threadIdx.x) >> 5;
    if (warp >= NN) return;
    int lane = threadIdx.x & 31;
    int g = lane >> 3, j = lane & 7;
    int node = warp;

    uint4 qq = ((const uint4*)(g_qh + (size_t)node * 64))[j];
    float2 q0 = __half22float2(*(__half2*)&qq.x);
    float2 q1 = __half22float2(*(__half2*)&qq.y);
    float2 q2 = __half22float2(*(__half2*)&qq.z);
    float2 q3 = __half22float2(*(__half2*)&qq.w);
    float4 qa = make_float4(q0.x, q0.y, q1.x, q1.y);
    float4 qb = make_float4(q2.x, q2.y, q3.x, q3.y);

    int beg = g_rowstart[node];
    int end = g_rowstart[node + 1];

    float a[8] = {0.f, 0.f, 0.f, 0.f, 0.f, 0.f, 0.f, 0.f};
    float den = 0.f;

    if (beg < end) {
        int lim = end - 1;
        int nA = g_csrsrc[min(beg + g, lim)];
        int nB = g_csrsrc[min(beg + 4 + g, lim)];
        int nC = g_csrsrc[min(beg + 8 + g, lim)];
        int nD = g_csrsrc[min(beg + 12 + g, lim)];
        for (int i = beg; i < end; i += 16) {
            int sA = nA, sB = nB, sC = nC, sD = nD;
            int ni = i + 16;
            nA = g_csrsrc[min(ni + g, lim)];
            nB = g_csrsrc[min(ni + 4 + g, lim)];
            nC = g_csrsrc[min(ni + 8 + g, lim)];
            nD = g_csrsrc[min(ni + 12 + g, lim)];

            const uint4* kvA = (const uint4*)(g_kvh + (size_t)sA * 128);
            const uint4* kvB = (const uint4*)(g_kvh + (size_t)sB * 128);
            const uint4* kvC = (const uint4*)(g_kvh + (size_t)sC * 128);
            const uint4* kvD = (const uint4*)(g_kvh + (size_t)sD * 128);
            uint4 kA = kvA[j], kB = kvB[j], kC = kvC[j], kD = kvD[j];
            uint4 vA = kvA[8 + j], vB = kvB[8 + j], vC = kvC[8 + j], vD = kvD[8 + j];

            float pA = dot8(qa, qb, kA);
            float pB = dot8(qa, qb, kB);
            float pC = dot8(qa, qb, kC);
            float pD = dot8(qa, qb, kD);
            pA += __shfl_xor_sync(0xffffffffu, pA, 1);
            pB += __shfl_xor_sync(0xffffffffu, pB, 1);
            pC += __shfl_xor_sync(0xffffffffu, pC, 1);
            pD += __shfl_xor_sync(0xffffffffu, pD, 1);
            float eA = (i + g < end)      ? __expf(pA * 0.25f) : 0.f;
            float eB = (i + 4 + g < end)  ? __expf(pB * 0.25f) : 0.f;
            float eC = (i + 8 + g < end)  ? __expf(pC * 0.25f) : 0.f;
            float eD = (i + 12 + g < end) ? __expf(pD * 0.25f) : 0.f;
            acc8(a, eA, vA);
            acc8(a, eB, vB);
            acc8(a, eC, vC);
            acc8(a, eD, vD);
            den += (eA + eB) + (eC + eD);
        }
    }

#pragma unroll
    for (int c = 0; c < 8; c++) {
        a[c] += __shfl_xor_sync(0xffffffffu, a[c], 8);
        a[c] += __shfl_xor_sync(0xffffffffu, a[c], 16);
    }
    den += __shfl_xor_sync(0xffffffffu, den, 8);
    den += __shfl_xor_sync(0xffffffffu, den, 16);

    if (g == 0) {
        float inv = (den > 0.f) ? __frcp_rn(den) : 0.f;
        float4 ska = ((const float4*)(g_skip + (size_t)node * 64))[2 * j];
        float4 skb = ((const float4*)(g_skip + (size_t)node * 64))[2 * j + 1];
        float4 bga = ((const float4*)bg)[2 * j],  bgb = ((const float4*)bg)[2 * j + 1];
        float4 bba = ((const float4*)bb)[2 * j],  bbb = ((const float4*)bb)[2 * j + 1];
        float4 bma = ((const float4*)bm)[2 * j],  bmb = ((const float4*)bm)[2 * j + 1];
        float4 bva = ((const float4*)bvv)[2 * j], bvb = ((const float4*)bvv)[2 * j + 1];
        float o[8];
        o[0] = a[0] * inv + ska.x; o[1] = a[1] * inv + ska.y;
        o[2] = a[2] * inv + ska.z; o[3] = a[3] * inv + ska.w;
        o[4] = a[4] * inv + skb.x; o[5] = a[5] * inv + skb.y;
        o[6] = a[6] * inv + skb.z; o[7] = a[7] * inv + skb.w;
        o[0] = fmaxf((o[0] - bma.x) * rsqrtf(bva.x + EPSV) * bga.x + bba.x, 0.f);
        o[1] = fmaxf((o[1] - bma.y) * rsqrtf(bva.y + EPSV) * bga.y + bba.y, 0.f);
        o[2] = fmaxf((o[2] - bma.z) * rsqrtf(bva.z + EPSV) * bga.z + bba.z, 0.f);
        o[3] = fmaxf((o[3] - bma.w) * rsqrtf(bva.w + EPSV) * bga.w + bba.w, 0.f);
        o[4] = fmaxf((o[4] - bmb.x) * rsqrtf(bvb.x + EPSV) * bgb.x + bbb.x, 0.f);
        o[5] = fmaxf((o[5] - bmb.y) * rsqrtf(bvb.y + EPSV) * bgb.y + bbb.y, 0.f);
        o[6] = fmaxf((o[6] - bmb.z) * rsqrtf(bvb.z + EPSV) * bgb.z + bbb.z, 0.f);
        o[7] = fmaxf((o[7] - bmb.w) * rsqrtf(bvb.w + EPSV) * bgb.w + bbb.w, 0.f);
        float4* xo = (float4*)(g_x + (size_t)node * 64);
        xo[2 * j]     = make_float4(o[0], o[1], o[2], o[3]);
        xo[2 * j + 1] = make_float4(o[4], o[5], o[6], o[7]);
    }
}

// ================= head GEMM (also re-zeros g_cnt for the next call) =================
__global__ void k_head(const float* __restrict__ Wh, const float* __restrict__ bh,
                       float* __restrict__ out) {
    __shared__ float xs[32 * 64];
    __shared__ float ws[64 * 32];
    int t = threadIdx.x;
    int gid = blockIdx.x * blockDim.x + t;
    if (gid < NN) g_cnt[gid] = 0;            // prep histogram for next call
    int node0 = blockIdx.x * 32;
    const float4* xsrc = (const float4*)(g_x + (size_t)node0 * 64);
    ((float4*)xs)[t]       = xsrc[t];
    ((float4*)xs)[t + 256] = xsrc[t + 256];
    ((float4*)ws)[t]       = ((const float4*)Wh)[t];
    ((float4*)ws)[t + 256] = ((const float4*)Wh)[t + 256];
    __syncthreads();
    int col = t & 31, nr = t >> 5;
    float a0, a1, a2, a3;
    a0 = a1 = a2 = a3 = bh[col];
#pragma unroll 8
    for (int kk = 0; kk < 64; kk++) {
        float w = ws[kk * 32 + col];
        a0 = fmaf(xs[nr * 64 + kk],        w, a0);
        a1 = fmaf(xs[(nr + 8) * 64 + kk],  w, a1);
        a2 = fmaf(xs[(nr + 16) * 64 + kk], w, a2);
        a3 = fmaf(xs[(nr + 24) * 64 + kk], w, a3);
    }
    out[(size_t)(node0 + nr) * 32 + col]      = a0;
    out[(size_t)(node0 + nr + 8) * 32 + col]  = a1;
    out[(size_t)(node0 + nr + 16) * 32 + col] = a2;
    out[(size_t)(node0 + nr + 24) * 32 + col] = a3;
}

// ================= launch =================
extern "C" void kernel_launch(void* const* d_in, const int* in_sizes, int n_in,
                              void* d_out, int out_size) {
    const float* x    = (const float*)d_in[0];
    const int*   ei   = (const int*)  d_in[1];
    const float* Wq   = (const float*)d_in[2];
    const float* bq   = (const float*)d_in[3];
    const float* Wk   = (const float*)d_in[4];
    const float* bk   = (const float*)d_in[5];
    const float* Wv   = (const float*)d_in[6];
    const float* bv   = (const float*)d_in[7];
    const float* Ws   = (const float*)d_in[8];
    const float* bs   = (const float*)d_in[9];
    const float* bn_g = (const float*)d_in[10];
    const float* bn_b = (const float*)d_in[11];
    const float* bn_m = (const float*)d_in[12];
    const float* bn_v = (const float*)d_in[13];
    const float* Wh   = (const float*)d_in[14];
    const float* bh   = (const float*)d_in[15];
    float* out = (float*)d_out;

    const int NB = (NN + 255) / 256;           // 391
    const int GA = (NN * 32 + 255) / 256;      // warp per node
    const int GH = NN / 32;                    // 3125

    uint4* wf_base;
    cudaGetSymbolAddress((void**)&wf_base, g_wf);

    k_prep1<<<EB + WPREPB, 256>>>(ei, Wq, Wk, Wv, Ws);            // 1: hist + wprep
    k_scan1<<<SBLK, 1024>>>();                                     // 2
    k_scan_fix<<<NB, 256>>>();                                     // 3
    k_gemm_fused<<<GR2, 256>>>(x, wf_base, bq, bk, bv, bs);        // 4: gemm L0 (profiled)
    k_scatter<<<EB, 256>>>(ei);                                    // 5
    k_attn<<<GA, 256>>>(bn_g, bn_b, bn_m, bn_v);                   // 6

    for (int l = 1; l < 3; l++) {
        size_t bo = (size_t)l * HID;
        k_gemm_fused<<<GR2, 256>>>(nullptr, wf_base + (size_t)l * 4096,
                                   bq + bo, bk + bo, bv + bo, bs + bo);
        k_attn<<<GA, 256>>>(bn_g + bo, bn_b + bo, bn_m + bo, bn_v + bo);
    }
    k_head<<<GH, 256>>>(Wh, bh, out);
}

// round 14
// speedup vs baseline: 1.0810x; 1.0276x over previous
#include <cuda_runtime.h>
#include <cuda_fp16.h>
#include <cuda_bf16.h>
#include <cstdint>

#define NN 100000
#define EE 1600000
#define HID 64
#define OC 32
#define EPSV 1e-5f
#define EB 6250          // hist/scatter blocks (EE/256)
#define WPREPB 48        // wprep blocks (3*4096/256)
#define SBLK 98          // scan blocks ((NN+1023)/1024)
#define GR2 782          // gemm blocks: 4 tiles of 32 rows each (782*128 >= NN)

// ---------------- scratch (device globals; zero-initialized at module load) ----------------
__device__ __half g_qh[(size_t)NN * HID];    // q in fp16 (128 B/node)
__device__ __half g_skip[(size_t)NN * HID];  // skip in fp16 (128 B/node)
__device__ float  g_x[(size_t)NN * HID];
__device__ __half g_kvh[(size_t)NN * 128];   // per node: k[64] halves then v[64] halves (256 B)
__device__ uint4  g_wf[3 * 4096];            // per layer: 4 sel x 4 kt x 8 nt x 32 lanes {bh0,bh1,bl0,bl1}

__device__ int g_cnt[NN];                    // zeroed by k_head at end of every call
__device__ int g_rowstart[NN + 1];
__device__ int g_cursor[NN];
__device__ int g_csrsrc[EE];
__device__ int g_bsum[128];

// ================= GEMM helpers =================
__device__ __forceinline__ void mma_bf16(float* c, uint32_t a0, uint32_t a1,
                                         uint32_t a2, uint32_t a3,
                                         uint32_t b0, uint32_t b1) {
    asm volatile("mma.sync.aligned.m16n8k16.row.col.f32.bf16.bf16.f32 "
                 "{%0,%1,%2,%3}, {%4,%5,%6,%7}, {%8,%9}, {%0,%1,%2,%3};"
                 : "+f"(c[0]), "+f"(c[1]), "+f"(c[2]), "+f"(c[3])
                 : "r"(a0), "r"(a1), "r"(a2), "r"(a3), "r"(b0), "r"(b1));
}
__device__ __forceinline__ uint32_t pack_hi(float a, float b) {
    __nv_bfloat162 h = __floats2bfloat162_rn(a, b);
    return *(uint32_t*)&h;
}
__device__ __forceinline__ uint32_t pack_lo(float a, float b, uint32_t hi) {
    __nv_bfloat162 h = *(__nv_bfloat162*)&hi;
    __nv_bfloat162 l = __floats2bfloat162_rn(a - __bfloat162float(h.x),
                                             b - __bfloat162float(h.y));
    return *(uint32_t*)&l;
}

#define XSTR 72   // bf16 row stride: conflict-free

// gemm body: computes 32 rows starting at row0 for all 4 output matrices.
__device__ __forceinline__ void gemm_body(
        const float* __restrict__ x, const uint4* __restrict__ wf, int row0,
        const float* __restrict__ bq, const float* __restrict__ bk,
        const float* __restrict__ bv, const float* __restrict__ bs,
        __nv_bfloat16* xh, __nv_bfloat16* xl) {
    int t = threadIdx.x;
#pragma unroll
    for (int i = 0; i < 2; i++) {
        int idx = t + 256 * i;
        int r = idx >> 4, c4 = idx & 15;
        float4 val = ((const float4*)(x + (size_t)(row0 + r) * 64))[c4];
        uint32_t h01 = pack_hi(val.x, val.y);
        uint32_t h23 = pack_hi(val.z, val.w);
        uint32_t l01 = pack_lo(val.x, val.y, h01);
        uint32_t l23 = pack_lo(val.z, val.w, h23);
        *(uint2*)(&xh[r * XSTR + c4 * 4]) = make_uint2(h01, h23);
        *(uint2*)(&xl[r * XSTR + c4 * 4]) = make_uint2(l01, l23);
    }
    __syncthreads();

    int wid = t >> 5, lane = t & 31;
    int tig = lane & 3, grp = lane >> 2;
    int cloc = wid * 8 + 2 * tig;

    float acc[4][2][4];
    {
        const float* biases[4] = {bq, bk, bv, bs};
#pragma unroll
        for (int sel = 0; sel < 4; sel++) {
            float b0 = biases[sel][cloc], b1 = biases[sel][cloc + 1];
#pragma unroll
            for (int mt = 0; mt < 2; mt++) {
                acc[sel][mt][0] = b0; acc[sel][mt][1] = b1;
                acc[sel][mt][2] = b0; acc[sel][mt][3] = b1;
            }
        }
    }

#pragma unroll 1
    for (int kt = 0; kt < 4; kt++) {
        uint4 bf[4];
#pragma unroll
        for (int sel = 0; sel < 4; sel++)
            bf[sel] = wf[((sel * 4 + kt) * 8 + wid) * 32 + lane];
        int k = kt * 16 + tig * 2;
#pragma unroll
        for (int mt = 0; mt < 2; mt++) {
            int r = mt * 16 + grp;
            uint32_t h0 = *(uint32_t*)&xh[r * XSTR + k];
            uint32_t h1 = *(uint32_t*)&xh[(r + 8) * XSTR + k];
            uint32_t h2 = *(uint32_t*)&xh[r * XSTR + k + 8];
            uint32_t h3 = *(uint32_t*)&xh[(r + 8) * XSTR + k + 8];
            uint32_t l0 = *(uint32_t*)&xl[r * XSTR + k];
            uint32_t l1 = *(uint32_t*)&xl[(r + 8) * XSTR + k];
            uint32_t l2 = *(uint32_t*)&xl[r * XSTR + k + 8];
            uint32_t l3 = *(uint32_t*)&xl[(r + 8) * XSTR + k + 8];
#pragma unroll
            for (int sel = 0; sel < 4; sel++) {
                mma_bf16(acc[sel][mt], h0, h1, h2, h3, bf[sel].x, bf[sel].y);
                mma_bf16(acc[sel][mt], h0, h1, h2, h3, bf[sel].z, bf[sel].w);
                mma_bf16(acc[sel][mt], l0, l1, l2, l3, bf[sel].x, bf[sel].y);
            }
        }
    }

#pragma unroll
    for (int sel = 0; sel < 4; sel++) {
#pragma unroll
        for (int mt = 0; mt < 2; mt++) {
            int r0g = row0 + mt * 16 + grp;
            int r1g = r0g + 8;
            float* a = acc[sel][mt];
            if (sel == 0) {
                *(__half2*)(g_qh + (size_t)r0g * 64 + cloc) = __floats2half2_rn(a[0], a[1]);
                *(__half2*)(g_qh + (size_t)r1g * 64 + cloc) = __floats2half2_rn(a[2], a[3]);
            } else if (sel == 3) {
                *(__half2*)(g_skip + (size_t)r0g * 64 + cloc) = __floats2half2_rn(a[0], a[1]);
                *(__half2*)(g_skip + (size_t)r1g * 64 + cloc) = __floats2half2_rn(a[2], a[3]);
            } else {
                int off = (sel == 2) ? 64 : 0;
                *(__half2*)(g_kvh + (size_t)r0g * 128 + off + cloc) = __floats2half2_rn(a[0], a[1]);
                *(__half2*)(g_kvh + (size_t)r1g * 128 + off + cloc) = __floats2half2_rn(a[2], a[3]);
            }
        }
    }
}

// ================= launch 1: hist + W-frag prep (disjoint block ranges) =================
__global__ void k_prep1(const int* __restrict__ ei,
                        const float* __restrict__ Wq, const float* __restrict__ Wk,
                        const float* __restrict__ Wv, const float* __restrict__ Ws) {
    int b = blockIdx.x;
    if (b < EB) {
        int e = b * 256 + threadIdx.x;
        if (e < EE) atomicAdd(&g_cnt[ei[EE + e]], 1);
        return;
    }
    int t = (b - EB) * 256 + threadIdx.x;
    if (t >= 3 * 4096) return;
    int lane  = t & 31;
    int nt    = (t >> 5) & 7;
    int kt    = (t >> 8) & 3;
    int sel   = (t >> 10) & 3;
    int layer = t >> 12;
    const float* Wb = (sel == 0) ? Wq : (sel == 1) ? Wk : (sel == 2) ? Wv : Ws;
    const float* W = Wb + (size_t)layer * HID * HID;
    int grp = lane >> 2, tig = lane & 3;
    int n  = nt * 8 + grp;
    int k0 = kt * 16 + tig * 2;
    float b00 = W[k0 * 64 + n],       b01 = W[(k0 + 1) * 64 + n];
    float b10 = W[(k0 + 8) * 64 + n], b11 = W[(k0 + 9) * 64 + n];
    uint32_t h0 = pack_hi(b00, b01), h1 = pack_hi(b10, b11);
    uint32_t l0 = pack_lo(b00, b01, h0), l1 = pack_lo(b10, b11, h1);
    uint4 o; o.x = h0; o.y = h1; o.z = l0; o.w = l1;
    g_wf[t] = o;
}

// ================= launch 2: scan stage 1 =================
__global__ void k_scan1() {
    __shared__ int sh[1024];
    int i = blockIdx.x * 1024 + threadIdx.x;
    int v = (i < NN) ? g_cnt[i] : 0;
    sh[threadIdx.x] = v;
    __syncthreads();
    for (int off = 1; off < 1024; off <<= 1) {
        int t = (threadIdx.x >= off) ? sh[threadIdx.x - off] : 0;
        __syncthreads();
        sh[threadIdx.x] += t;
        __syncthreads();
    }
    if (i < NN) g_rowstart[i] = sh[threadIdx.x] - v;
    if (threadIdx.x == 1023) g_bsum[blockIdx.x] = sh[1023];
}

// ================= launch 3: scan fixup =================
__global__ void k_scan_fix() {
    __shared__ int sh[128];
    int t = threadIdx.x;
    if (t < 128) sh[t] = (t < SBLK) ? g_bsum[t] : 0;
    __syncthreads();
    for (int off = 1; off < 128; off <<= 1) {
        int u = (t < 128 && t >= off) ? sh[t - off] : 0;
        __syncthreads();
        if (t < 128) sh[t] += u;
        __syncthreads();
    }
    __shared__ int pre[128];
    if (t < 128) pre[t] = sh[t] - ((t < SBLK) ? g_bsum[t] : 0);
    __syncthreads();
    int i = blockIdx.x * blockDim.x + t;
    if (i < NN) {
        int rs = g_rowstart[i] + pre[i >> 10];
        g_rowstart[i] = rs;
        g_cursor[i] = rs;
    }
    if (i == 0) g_rowstart[NN] = EE;
}

// ================= launch 4: gemm (4 x 32-row tiles per block; 3 CTAs/SM) =================
__global__ void __launch_bounds__(256, 3) k_gemm_fused(
        const float* __restrict__ xin, const uint4* __restrict__ wf,
        const float* __restrict__ bq, const float* __restrict__ bk,
        const float* __restrict__ bv, const float* __restrict__ bs) {
    __shared__ __nv_bfloat16 xh[32 * XSTR];
    __shared__ __nv_bfloat16 xl[32 * XSTR];
    const float* x = xin ? xin : g_x;
#pragma unroll 1
    for (int it = 0; it < 4; it++) {
        int row0 = blockIdx.x * 128 + it * 32;
        if (row0 >= NN) break;
        if (it) __syncthreads();
        gemm_body(x, wf, row0, bq, bk, bv, bs, xh, xl);
    }
}

// ================= launch 5: scatter (standalone, high occupancy) =================
__global__ void k_scatter(const int* __restrict__ ei) {
    int e = blockIdx.x * blockDim.x + threadIdx.x;
    if (e >= EE) return;
    int s = ei[e], d = ei[EE + e];
    int pos = atomicAdd(&g_cursor[d], 1);
    g_csrsrc[pos] = s;
}

// ================= fused attention: 16-edge batches, __ldcg gathers =================
__device__ __forceinline__ float dot8(const float4& qa, const float4& qb, const uint4& kk) {
    float2 k0 = __half22float2(*(__half2*)&kk.x);
    float2 k1 = __half22float2(*(__half2*)&kk.y);
    float2 k2 = __half22float2(*(__half2*)&kk.z);
    float2 k3 = __half22float2(*(__half2*)&kk.w);
    return qa.x * k0.x + qa.y * k0.y + qa.z * k1.x + qa.w * k1.y
         + qb.x * k2.x + qb.y * k2.y + qb.z * k3.x + qb.w * k3.y;
}
__device__ __forceinline__ void acc8(float* a, float ex, const uint4& vv) {
    float2 v0 = __half22float2(*(__half2*)&vv.x);
    float2 v1 = __half22float2(*(__half2*)&vv.y);
    float2 v2 = __half22float2(*(__half2*)&vv.z);
    float2 v3 = __half22float2(*(__half2*)&vv.w);
    a[0] = fmaf(ex, v0.x, a[0]); a[1] = fmaf(ex, v0.y, a[1]);
    a[2] = fmaf(ex, v1.x, a[2]); a[3] = fmaf(ex, v1.y, a[3]);
    a[4] = fmaf(ex, v2.x, a[4]); a[5] = fmaf(ex, v2.y, a[5]);
    a[6] = fmaf(ex, v3.x, a[6]); a[7] = fmaf(ex, v3.y, a[7]);
}

__global__ void k_attn(const float* __restrict__ bg, const float* __restrict__ bb,
                       const float* __restrict__ bm, const float* __restrict__ bvv) {
    int warp = (blockIdx.x * blockDim.x + threadIdx.x) >> 5;
    if (warp >= NN) return;
    int lane = threadIdx.x & 31;
    int g = lane >> 3, j = lane & 7;
    int node = warp;

    uint4 qq = ((const uint4*)(g_qh + (size_t)node * 64))[j];
    float2 q0 = __half22float2(*(__half2*)&qq.x);
    float2 q1 = __half22float2(*(__half2*)&qq.y);
    float2 q2 = __half22float2(*(__half2*)&qq.z);
    float2 q3 = __half22float2(*(__half2*)&qq.w);
    float4 qa = make_float4(q0.x, q0.y, q1.x, q1.y);
    float4 qb = make_float4(q2.x, q2.y, q3.x, q3.y);

    int beg = g_rowstart[node];
    int end = g_rowstart[node + 1];

    float a[8] = {0.f, 0.f, 0.f, 0.f, 0.f, 0.f, 0.f, 0.f};
    float den = 0.f;

    if (beg < end) {
        int lim = end - 1;
        int nA = g_csrsrc[min(beg + g, lim)];
        int nB = g_csrsrc[min(beg + 4 + g, lim)];
        int nC = g_csrsrc[min(beg + 8 + g, lim)];
        int nD = g_csrsrc[min(beg + 12 + g, lim)];
        for (int i = beg; i < end; i += 16) {
            int sA = nA, sB = nB, sC = nC, sD = nD;
            int ni = i + 16;
            nA = g_csrsrc[min(ni + g, lim)];
            nB = g_csrsrc[min(ni + 4 + g, lim)];
            nC = g_csrsrc[min(ni + 8 + g, lim)];
            nD = g_csrsrc[min(ni + 12 + g, lim)];

            const uint4* kvA = (const uint4*)(g_kvh + (size_t)sA * 128);
            const uint4* kvB = (const uint4*)(g_kvh + (size_t)sB * 128);
            const uint4* kvC = (const uint4*)(g_kvh + (size_t)sC * 128);
            const uint4* kvD = (const uint4*)(g_kvh + (size_t)sD * 128);
            uint4 kA = __ldcg(kvA + j),     kB = __ldcg(kvB + j);
            uint4 kC = __ldcg(kvC + j),     kD = __ldcg(kvD + j);
            uint4 vA = __ldcg(kvA + 8 + j), vB = __ldcg(kvB + 8 + j);
            uint4 vC = __ldcg(kvC + 8 + j), vD = __ldcg(kvD + 8 + j);

            float pA = dot8(qa, qb, kA);
            float pB = dot8(qa, qb, kB);
            float pC = dot8(qa, qb, kC);
            float pD = dot8(qa, qb, kD);
            pA += __shfl_xor_sync(0xffffffffu, pA, 1);
            pB += __shfl_xor_sync(0xffffffffu, pB, 1);
            pC += __shfl_xor_sync(0xffffffffu, pC, 1);
            pD += __shfl_xor_sync(0xffffffffu, pD, 1);
            float eA = (i + g < end)      ? __expf(pA * 0.25f) : 0.f;
            float eB = (i + 4 + g < end)  ? __expf(pB * 0.25f) : 0.f;
            float eC = (i + 8 + g < end)  ? __expf(pC * 0.25f) : 0.f;
            float eD = (i + 12 + g < end) ? __expf(pD * 0.25f) : 0.f;
            acc8(a, eA, vA);
            acc8(a, eB, vB);
            acc8(a, eC, vC);
            acc8(a, eD, vD);
            den += (eA + eB) + (eC + eD);
        }
    }

#pragma unroll
    for (int c = 0; c < 8; c++) {
        a[c] += __shfl_xor_sync(0xffffffffu, a[c], 8);
        a[c] += __shfl_xor_sync(0xffffffffu, a[c], 16);
    }
    den += __shfl_xor_sync(0xffffffffu, den, 8);
    den += __shfl_xor_sync(0xffffffffu, den, 16);

    if (g == 0) {
        float inv = (den > 0.f) ? __frcp_rn(den) : 0.f;
        uint4 sk = __ldcg(((const uint4*)(g_skip + (size_t)node * 64)) + j);
        float2 s0 = __half22float2(*(__half2*)&sk.x);
        float2 s1 = __half22float2(*(__half2*)&sk.y);
        float2 s2 = __half22float2(*(__half2*)&sk.z);
        float2 s3 = __half22float2(*(__half2*)&sk.w);
        float4 bga = ((const float4*)bg)[2 * j],  bgb = ((const float4*)bg)[2 * j + 1];
        float4 bba = ((const float4*)bb)[2 * j],  bbb = ((const float4*)bb)[2 * j + 1];
        float4 bma = ((const float4*)bm)[2 * j],  bmb = ((const float4*)bm)[2 * j + 1];
        float4 bva = ((const float4*)bvv)[2 * j], bvb = ((const float4*)bvv)[2 * j + 1];
        float o[8];
        o[0] = a[0] * inv + s0.x; o[1] = a[1] * inv + s0.y;
        o[2] = a[2] * inv + s1.x; o[3] = a[3] * inv + s1.y;
        o[4] = a[4] * inv + s2.x; o[5] = a[5] * inv + s2.y;
        o[6] = a[6] * inv + s3.x; o[7] = a[7] * inv + s3.y;
        o[0] = fmaxf((o[0] - bma.x) * rsqrtf(bva.x + EPSV) * bga.x + bba.x, 0.f);
        o[1] = fmaxf((o[1] - bma.y) * rsqrtf(bva.y + EPSV) * bga.y + bba.y, 0.f);
        o[2] = fmaxf((o[2] - bma.z) * rsqrtf(bva.z + EPSV) * bga.z + bba.z, 0.f);
        o[3] = fmaxf((o[3] - bma.w) * rsqrtf(bva.w + EPSV) * bga.w + bba.w, 0.f);
        o[4] = fmaxf((o[4] - bmb.x) * rsqrtf(bvb.x + EPSV) * bgb.x + bbb.x, 0.f);
        o[5] = fmaxf((o[5] - bmb.y) * rsqrtf(bvb.y + EPSV) * bgb.y + bbb.y, 0.f);
        o[6] = fmaxf((o[6] - bmb.z) * rsqrtf(bvb.z + EPSV) * bgb.z + bbb.z, 0.f);
        o[7] = fmaxf((o[7] - bmb.w) * rsqrtf(bvb.w + EPSV) * bgb.w + bbb.w, 0.f);
        float4* xo = (float4*)(g_x + (size_t)node * 64);
        xo[2 * j]     = make_float4(o[0], o[1], o[2], o[3]);
        xo[2 * j + 1] = make_float4(o[4], o[5], o[6], o[7]);
    }
}

// ================= head GEMM (also re-zeros g_cnt for the next call) =================
__global__ void k_head(const float* __restrict__ Wh, const float* __restrict__ bh,
                       float* __restrict__ out) {
    __shared__ float xs[32 * 64];
    __shared__ float ws[64 * 32];
    int t = threadIdx.x;
    int gid = blockIdx.x * blockDim.x + t;
    if (gid < NN) g_cnt[gid] = 0;            // prep histogram for next call
    int node0 = blockIdx.x * 32;
    const float4* xsrc = (const float4*)(g_x + (size_t)node0 * 64);
    ((float4*)xs)[t]       = xsrc[t];
    ((float4*)xs)[t + 256] = xsrc[t + 256];
    ((float4*)ws)[t]       = ((const float4*)Wh)[t];
    ((float4*)ws)[t + 256] = ((const float4*)Wh)[t + 256];
    __syncthreads();
    int col = t & 31, nr = t >> 5;
    float a0, a1, a2, a3;
    a0 = a1 = a2 = a3 = bh[col];
#pragma unroll 8
    for (int kk = 0; kk < 64; kk++) {
        float w = ws[kk * 32 + col];
        a0 = fmaf(xs[nr * 64 + kk],        w, a0);
        a1 = fmaf(xs[(nr + 8) * 64 + kk],  w, a1);
        a2 = fmaf(xs[(nr + 16) * 64 + kk], w, a2);
        a3 = fmaf(xs[(nr + 24) * 64 + kk], w, a3);
    }
    out[(size_t)(node0 + nr) * 32 + col]      = a0;
    out[(size_t)(node0 + nr + 8) * 32 + col]  = a1;
    out[(size_t)(node0 + nr + 16) * 32 + col] = a2;
    out[(size_t)(node0 + nr + 24) * 32 + col] = a3;
}

// ================= launch =================
extern "C" void kernel_launch(void* const* d_in, const int* in_sizes, int n_in,
                              void* d_out, int out_size) {
    const float* x    = (const float*)d_in[0];
    const int*   ei   = (const int*)  d_in[1];
    const float* Wq   = (const float*)d_in[2];
    const float* bq   = (const float*)d_in[3];
    const float* Wk   = (const float*)d_in[4];
    const float* bk   = (const float*)d_in[5];
    const float* Wv   = (const float*)d_in[6];
    const float* bv   = (const float*)d_in[7];
    const float* Ws   = (const float*)d_in[8];
    const float* bs   = (const float*)d_in[9];
    const float* bn_g = (const float*)d_in[10];
    const float* bn_b = (const float*)d_in[11];
    const float* bn_m = (const float*)d_in[12];
    const float* bn_v = (const float*)d_in[13];
    const float* Wh   = (const float*)d_in[14];
    const float* bh   = (const float*)d_in[15];
    float* out = (float*)d_out;

    const int NB = (NN + 255) / 256;           // 391
    const int GA = (NN * 32 + 255) / 256;      // warp per node
    const int GH = NN / 32;                    // 3125

    uint4* wf_base;
    cudaGetSymbolAddress((void**)&wf_base, g_wf);

    k_prep1<<<EB + WPREPB, 256>>>(ei, Wq, Wk, Wv, Ws);            // 1: hist + wprep
    k_scan1<<<SBLK, 1024>>>();                                     // 2
    k_scan_fix<<<NB, 256>>>();                                     // 3
    k_gemm_fused<<<GR2, 256>>>(x, wf_base, bq, bk, bv, bs);        // 4: gemm L0 (profiled)
    k_scatter<<<EB, 256>>>(ei);                                    // 5
    k_attn<<<GA, 256>>>(bn_g, bn_b, bn_m, bn_v);                   // 6

    for (int l = 1; l < 3; l++) {
        size_t bo = (size_t)l * HID;
        k_gemm_fused<<<GR2, 256>>>(nullptr, wf_base + (size_t)l * 4096,
                                   bq + bo, bk + bo, bv + bo, bs + bo);
        k_attn<<<GA, 256>>>(bn_g + bo, bn_b + bo, bn_m + bo, bn_v + bo);
    }
    k_head<<<GH, 256>>>(Wh, bh, out);
}

// round 15
// speedup vs baseline: 1.2196x; 1.1282x over previous
#include <cuda_runtime.h>
#include <cuda_fp16.h>
#include <cuda_bf16.h>
#include <cstdint>

#define NN 100000
#define EE 1600000
#define HID 64
#define OC 32
#define EPSV 1e-5f
#define EB 6250          // hist/scatter blocks (EE/256)
#define WPREPB 48        // wprep blocks (3*4096/256)
#define SBLK 98          // scan blocks ((NN+1023)/1024)
#define GR2 782          // gemm blocks: 4 tiles of 32 rows each (782*128 >= NN)

// ---------------- scratch (device globals; zero-initialized at module load) ----------------
__device__ __half g_qh[(size_t)NN * HID];    // q in fp16 (128 B/node)
__device__ __half g_skip[(size_t)NN * HID];  // skip in fp16 (128 B/node)
__device__ float  g_x[(size_t)NN * HID];
__device__ __half g_kvh[(size_t)NN * 128];   // per node: k[64] halves then v[64] halves (256 B)
__device__ uint4  g_wf[3 * 4096];            // per layer: 4 sel x 4 kt x 8 nt x 32 lanes {bh0,bh1,bl0,bl1}

__device__ int g_cnt[NN];                    // zeroed by k_head at end of every call
__device__ int g_rowstart[NN + 1];
__device__ int g_cursor[NN];
__device__ int g_csrsrc[EE];
__device__ int g_bsum[128];

// ================= GEMM helpers =================
__device__ __forceinline__ void mma_bf16(float* c, uint32_t a0, uint32_t a1,
                                         uint32_t a2, uint32_t a3,
                                         uint32_t b0, uint32_t b1) {
    asm volatile("mma.sync.aligned.m16n8k16.row.col.f32.bf16.bf16.f32 "
                 "{%0,%1,%2,%3}, {%4,%5,%6,%7}, {%8,%9}, {%0,%1,%2,%3};"
                 : "+f"(c[0]), "+f"(c[1]), "+f"(c[2]), "+f"(c[3])
                 : "r"(a0), "r"(a1), "r"(a2), "r"(a3), "r"(b0), "r"(b1));
}
__device__ __forceinline__ uint32_t pack_hi(float a, float b) {
    __nv_bfloat162 h = __floats2bfloat162_rn(a, b);
    return *(uint32_t*)&h;
}
__device__ __forceinline__ uint32_t pack_lo(float a, float b, uint32_t hi) {
    __nv_bfloat162 h = *(__nv_bfloat162*)&hi;
    __nv_bfloat162 l = __floats2bfloat162_rn(a - __bfloat162float(h.x),
                                             b - __bfloat162float(h.y));
    return *(uint32_t*)&l;
}

#define XSTR 72   // bf16 row stride: conflict-free

// gemm body: computes 32 rows starting at row0 for all 4 output matrices.
__device__ __forceinline__ void gemm_body(
        const float* __restrict__ x, const uint4* __restrict__ wf, int row0,
        const float* __restrict__ bq, const float* __restrict__ bk,
        const float* __restrict__ bv, const float* __restrict__ bs,
        __nv_bfloat16* xh, __nv_bfloat16* xl) {
    int t = threadIdx.x;
#pragma unroll
    for (int i = 0; i < 2; i++) {
        int idx = t + 256 * i;
        int r = idx >> 4, c4 = idx & 15;
        float4 val = ((const float4*)(x + (size_t)(row0 + r) * 64))[c4];
        uint32_t h01 = pack_hi(val.x, val.y);
        uint32_t h23 = pack_hi(val.z, val.w);
        uint32_t l01 = pack_lo(val.x, val.y, h01);
        uint32_t l23 = pack_lo(val.z, val.w, h23);
        *(uint2*)(&xh[r * XSTR + c4 * 4]) = make_uint2(h01, h23);
        *(uint2*)(&xl[r * XSTR + c4 * 4]) = make_uint2(l01, l23);
    }
    __syncthreads();

    int wid = t >> 5, lane = t & 31;
    int tig = lane & 3, grp = lane >> 2;
    int cloc = wid * 8 + 2 * tig;

    float acc[4][2][4];
    {
        const float* biases[4] = {bq, bk, bv, bs};
#pragma unroll
        for (int sel = 0; sel < 4; sel++) {
            float b0 = biases[sel][cloc], b1 = biases[sel][cloc + 1];
#pragma unroll
            for (int mt = 0; mt < 2; mt++) {
                acc[sel][mt][0] = b0; acc[sel][mt][1] = b1;
                acc[sel][mt][2] = b0; acc[sel][mt][3] = b1;
            }
        }
    }

#pragma unroll 1
    for (int kt = 0; kt < 4; kt++) {
        uint4 bf[4];
#pragma unroll
        for (int sel = 0; sel < 4; sel++)
            bf[sel] = wf[((sel * 4 + kt) * 8 + wid) * 32 + lane];
        int k = kt * 16 + tig * 2;
#pragma unroll
        for (int mt = 0; mt < 2; mt++) {
            int r = mt * 16 + grp;
            uint32_t h0 = *(uint32_t*)&xh[r * XSTR + k];
            uint32_t h1 = *(uint32_t*)&xh[(r + 8) * XSTR + k];
            uint32_t h2 = *(uint32_t*)&xh[r * XSTR + k + 8];
            uint32_t h3 = *(uint32_t*)&xh[(r + 8) * XSTR + k + 8];
            uint32_t l0 = *(uint32_t*)&xl[r * XSTR + k];
            uint32_t l1 = *(uint32_t*)&xl[(r + 8) * XSTR + k];
            uint32_t l2 = *(uint32_t*)&xl[r * XSTR + k + 8];
            uint32_t l3 = *(uint32_t*)&xl[(r + 8) * XSTR + k + 8];
#pragma unroll
            for (int sel = 0; sel < 4; sel++) {
                mma_bf16(acc[sel][mt], h0, h1, h2, h3, bf[sel].x, bf[sel].y);
                mma_bf16(acc[sel][mt], h0, h1, h2, h3, bf[sel].z, bf[sel].w);
                mma_bf16(acc[sel][mt], l0, l1, l2, l3, bf[sel].x, bf[sel].y);
            }
        }
    }

#pragma unroll
    for (int sel = 0; sel < 4; sel++) {
#pragma unroll
        for (int mt = 0; mt < 2; mt++) {
            int r0g = row0 + mt * 16 + grp;
            int r1g = r0g + 8;
            float* a = acc[sel][mt];
            if (sel == 0) {
                *(__half2*)(g_qh + (size_t)r0g * 64 + cloc) = __floats2half2_rn(a[0], a[1]);
                *(__half2*)(g_qh + (size_t)r1g * 64 + cloc) = __floats2half2_rn(a[2], a[3]);
            } else if (sel == 3) {
                *(__half2*)(g_skip + (size_t)r0g * 64 + cloc) = __floats2half2_rn(a[0], a[1]);
                *(__half2*)(g_skip + (size_t)r1g * 64 + cloc) = __floats2half2_rn(a[2], a[3]);
            } else {
                int off = (sel == 2) ? 64 : 0;
                *(__half2*)(g_kvh + (size_t)r0g * 128 + off + cloc) = __floats2half2_rn(a[0], a[1]);
                *(__half2*)(g_kvh + (size_t)r1g * 128 + off + cloc) = __floats2half2_rn(a[2], a[3]);
            }
        }
    }
}

// ================= launch 1: hist + W-frag prep (disjoint block ranges) =================
__global__ void k_prep1(const int* __restrict__ ei,
                        const float* __restrict__ Wq, const float* __restrict__ Wk,
                        const float* __restrict__ Wv, const float* __restrict__ Ws) {
    int b = blockIdx.x;
    if (b < EB) {
        int e = b * 256 + threadIdx.x;
        if (e < EE) atomicAdd(&g_cnt[ei[EE + e]], 1);
        return;
    }
    int t = (b - EB) * 256 + threadIdx.x;
    if (t >= 3 * 4096) return;
    int lane  = t & 31;
    int nt    = (t >> 5) & 7;
    int kt    = (t >> 8) & 3;
    int sel   = (t >> 10) & 3;
    int layer = t >> 12;
    const float* Wb = (sel == 0) ? Wq : (sel == 1) ? Wk : (sel == 2) ? Wv : Ws;
    const float* W = Wb + (size_t)layer * HID * HID;
    int grp = lane >> 2, tig = lane & 3;
    int n  = nt * 8 + grp;
    int k0 = kt * 16 + tig * 2;
    float b00 = W[k0 * 64 + n],       b01 = W[(k0 + 1) * 64 + n];
    float b10 = W[(k0 + 8) * 64 + n], b11 = W[(k0 + 9) * 64 + n];
    uint32_t h0 = pack_hi(b00, b01), h1 = pack_hi(b10, b11);
    uint32_t l0 = pack_lo(b00, b01, h0), l1 = pack_lo(b10, b11, h1);
    uint4 o; o.x = h0; o.y = h1; o.z = l0; o.w = l1;
    g_wf[t] = o;
}

// ================= launch 2: scan stage 1 =================
__global__ void k_scan1() {
    __shared__ int sh[1024];
    int i = blockIdx.x * 1024 + threadIdx.x;
    int v = (i < NN) ? g_cnt[i] : 0;
    sh[threadIdx.x] = v;
    __syncthreads();
    for (int off = 1; off < 1024; off <<= 1) {
        int t = (threadIdx.x >= off) ? sh[threadIdx.x - off] : 0;
        __syncthreads();
        sh[threadIdx.x] += t;
        __syncthreads();
    }
    if (i < NN) g_rowstart[i] = sh[threadIdx.x] - v;
    if (threadIdx.x == 1023) g_bsum[blockIdx.x] = sh[1023];
}

// ================= launch 3: scan fixup =================
__global__ void k_scan_fix() {
    __shared__ int sh[128];
    int t = threadIdx.x;
    if (t < 128) sh[t] = (t < SBLK) ? g_bsum[t] : 0;
    __syncthreads();
    for (int off = 1; off < 128; off <<= 1) {
        int u = (t < 128 && t >= off) ? sh[t - off] : 0;
        __syncthreads();
        if (t < 128) sh[t] += u;
        __syncthreads();
    }
    __shared__ int pre[128];
    if (t < 128) pre[t] = sh[t] - ((t < SBLK) ? g_bsum[t] : 0);
    __syncthreads();
    int i = blockIdx.x * blockDim.x + t;
    if (i < NN) {
        int rs = g_rowstart[i] + pre[i >> 10];
        g_rowstart[i] = rs;
        g_cursor[i] = rs;
    }
    if (i == 0) g_rowstart[NN] = EE;
}

// ================= launch 4: gemm (4 x 32-row tiles per block; 3 CTAs/SM) =================
__global__ void __launch_bounds__(256, 3) k_gemm_fused(
        const float* __restrict__ xin, const uint4* __restrict__ wf,
        const float* __restrict__ bq, const float* __restrict__ bk,
        const float* __restrict__ bv, const float* __restrict__ bs) {
    __shared__ __nv_bfloat16 xh[32 * XSTR];
    __shared__ __nv_bfloat16 xl[32 * XSTR];
    const float* x = xin ? xin : g_x;
#pragma unroll 1
    for (int it = 0; it < 4; it++) {
        int row0 = blockIdx.x * 128 + it * 32;
        if (row0 >= NN) break;
        if (it) __syncthreads();
        gemm_body(x, wf, row0, bq, bk, bv, bs, xh, xl);
    }
}

// ================= launch 5: scatter (standalone, high occupancy) =================
__global__ void k_scatter(const int* __restrict__ ei) {
    int e = blockIdx.x * blockDim.x + threadIdx.x;
    if (e >= EE) return;
    int s = ei[e], d = ei[EE + e];
    int pos = atomicAdd(&g_cursor[d], 1);
    g_csrsrc[pos] = s;
}

// ================= fused attention: half2 math, 16-edge batches, __ldcg gathers =================
// Per edge (per lane): dot = hmul2 + 3x hfma2 + cvt + add + shfl; v-acc = 4x hfma2
// into per-lane half2 accumulators (each sees only deg/4 edges; cross-group
// reduction in fp32).
__device__ __forceinline__ float dot_h2(const __half2& q0, const __half2& q1,
                                        const __half2& q2, const __half2& q3,
                                        const uint4& kk) {
    __half2 d = __hmul2(q0, *(const __half2*)&kk.x);
    d = __hfma2(q1, *(const __half2*)&kk.y, d);
    d = __hfma2(q2, *(const __half2*)&kk.z, d);
    d = __hfma2(q3, *(const __half2*)&kk.w, d);
    float2 f = __half22float2(d);
    return f.x + f.y;
}
__device__ __forceinline__ void acc_h2(__half2* va, const __half2& eh, const uint4& vv) {
    va[0] = __hfma2(eh, *(const __half2*)&vv.x, va[0]);
    va[1] = __hfma2(eh, *(const __half2*)&vv.y, va[1]);
    va[2] = __hfma2(eh, *(const __half2*)&vv.z, va[2]);
    va[3] = __hfma2(eh, *(const __half2*)&vv.w, va[3]);
}

__global__ void k_attn(const float* __restrict__ bg, const float* __restrict__ bb,
                       const float* __restrict__ bm, const float* __restrict__ bvv) {
    int warp = (blockIdx.x * blockDim.x + threadIdx.x) >> 5;
    if (warp >= NN) return;
    int lane = threadIdx.x & 31;
    int g = lane >> 3, j = lane & 7;
    int node = warp;

    uint4 qq = ((const uint4*)(g_qh + (size_t)node * 64))[j];
    __half2 q0 = *(__half2*)&qq.x, q1 = *(__half2*)&qq.y;
    __half2 q2 = *(__half2*)&qq.z, q3 = *(__half2*)&qq.w;

    int beg = g_rowstart[node];
    int end = g_rowstart[node + 1];

    __half2 va[4];
    va[0] = va[1] = va[2] = va[3] = __float2half2_rn(0.f);
    float den = 0.f;

    if (beg < end) {
        int lim = end - 1;
        int nA = g_csrsrc[min(beg + g, lim)];
        int nB = g_csrsrc[min(beg + 4 + g, lim)];
        int nC = g_csrsrc[min(beg + 8 + g, lim)];
        int nD = g_csrsrc[min(beg + 12 + g, lim)];
        for (int i = beg; i < end; i += 16) {
            int sA = nA, sB = nB, sC = nC, sD = nD;
            int ni = i + 16;
            nA = g_csrsrc[min(ni + g, lim)];
            nB = g_csrsrc[min(ni + 4 + g, lim)];
            nC = g_csrsrc[min(ni + 8 + g, lim)];
            nD = g_csrsrc[min(ni + 12 + g, lim)];

            const uint4* kvA = (const uint4*)(g_kvh + (size_t)sA * 128);
            const uint4* kvB = (const uint4*)(g_kvh + (size_t)sB * 128);
            const uint4* kvC = (const uint4*)(g_kvh + (size_t)sC * 128);
            const uint4* kvD = (const uint4*)(g_kvh + (size_t)sD * 128);
            uint4 kA = __ldcg(kvA + j),     kB = __ldcg(kvB + j);
            uint4 kC = __ldcg(kvC + j),     kD = __ldcg(kvD + j);
            uint4 vA = __ldcg(kvA + 8 + j), vB = __ldcg(kvB + 8 + j);
            uint4 vC = __ldcg(kvC + 8 + j), vD = __ldcg(kvD + 8 + j);

            float pA = dot_h2(q0, q1, q2, q3, kA);
            float pB = dot_h2(q0, q1, q2, q3, kB);
            float pC = dot_h2(q0, q1, q2, q3, kC);
            float pD = dot_h2(q0, q1, q2, q3, kD);
            pA += __shfl_xor_sync(0xffffffffu, pA, 1);
            pB += __shfl_xor_sync(0xffffffffu, pB, 1);
            pC += __shfl_xor_sync(0xffffffffu, pC, 1);
            pD += __shfl_xor_sync(0xffffffffu, pD, 1);
            float eA = (i + g < end)      ? __expf(pA * 0.25f) : 0.f;
            float eB = (i + 4 + g < end)  ? __expf(pB * 0.25f) : 0.f;
            float eC = (i + 8 + g < end)  ? __expf(pC * 0.25f) : 0.f;
            float eD = (i + 12 + g < end) ? __expf(pD * 0.25f) : 0.f;
            acc_h2(va, __float2half2_rn(eA), vA);
            acc_h2(va, __float2half2_rn(eB), vB);
            acc_h2(va, __float2half2_rn(eC), vC);
            acc_h2(va, __float2half2_rn(eD), vD);
            den += (eA + eB) + (eC + eD);
        }
    }

    // convert half2 accumulators to fp32, reduce across the 4 edge groups
    float a[8];
    {
        float2 f0 = __half22float2(va[0]);
        float2 f1 = __half22float2(va[1]);
        float2 f2 = __half22float2(va[2]);
        float2 f3 = __half22float2(va[3]);
        a[0] = f0.x; a[1] = f0.y; a[2] = f1.x; a[3] = f1.y;
        a[4] = f2.x; a[5] = f2.y; a[6] = f3.x; a[7] = f3.y;
    }
#pragma unroll
    for (int c = 0; c < 8; c++) {
        a[c] += __shfl_xor_sync(0xffffffffu, a[c], 8);
        a[c] += __shfl_xor_sync(0xffffffffu, a[c], 16);
    }
    den += __shfl_xor_sync(0xffffffffu, den, 8);
    den += __shfl_xor_sync(0xffffffffu, den, 16);

    if (g == 0) {
        float inv = (den > 0.f) ? __frcp_rn(den) : 0.f;
        uint4 sk = __ldcg(((const uint4*)(g_skip + (size_t)node * 64)) + j);
        float2 s0 = __half22float2(*(__half2*)&sk.x);
        float2 s1 = __half22float2(*(__half2*)&sk.y);
        float2 s2 = __half22float2(*(__half2*)&sk.z);
        float2 s3 = __half22float2(*(__half2*)&sk.w);
        float4 bga = ((const float4*)bg)[2 * j],  bgb = ((const float4*)bg)[2 * j + 1];
        float4 bba = ((const float4*)bb)[2 * j],  bbb = ((const float4*)bb)[2 * j + 1];
        float4 bma = ((const float4*)bm)[2 * j],  bmb = ((const float4*)bm)[2 * j + 1];
        float4 bva = ((const float4*)bvv)[2 * j], bvb = ((const float4*)bvv)[2 * j + 1];
        float o[8];
        o[0] = a[0] * inv + s0.x; o[1] = a[1] * inv + s0.y;
        o[2] = a[2] * inv + s1.x; o[3] = a[3] * inv + s1.y;
        o[4] = a[4] * inv + s2.x; o[5] = a[5] * inv + s2.y;
        o[6] = a[6] * inv + s3.x; o[7] = a[7] * inv + s3.y;
        o[0] = fmaxf((o[0] - bma.x) * rsqrtf(bva.x + EPSV) * bga.x + bba.x, 0.f);
        o[1] = fmaxf((o[1] - bma.y) * rsqrtf(bva.y + EPSV) * bga.y + bba.y, 0.f);
        o[2] = fmaxf((o[2] - bma.z) * rsqrtf(bva.z + EPSV) * bga.z + bba.z, 0.f);
        o[3] = fmaxf((o[3] - bma.w) * rsqrtf(bva.w + EPSV) * bga.w + bba.w, 0.f);
        o[4] = fmaxf((o[4] - bmb.x) * rsqrtf(bvb.x + EPSV) * bgb.x + bbb.x, 0.f);
        o[5] = fmaxf((o[5] - bmb.y) * rsqrtf(bvb.y + EPSV) * bgb.y + bbb.y, 0.f);
        o[6] = fmaxf((o[6] - bmb.z) * rsqrtf(bvb.z + EPSV) * bgb.z + bbb.z, 0.f);
        o[7] = fmaxf((o[7] - bmb.w) * rsqrtf(bvb.w + EPSV) * bgb.w + bbb.w, 0.f);
        float4* xo = (float4*)(g_x + (size_t)node * 64);
        xo[2 * j]     = make_float4(o[0], o[1], o[2], o[3]);
        xo[2 * j + 1] = make_float4(o[4], o[5], o[6], o[7]);
    }
}

// ================= head GEMM (also re-zeros g_cnt for the next call) =================
__global__ void k_head(const float* __restrict__ Wh, const float* __restrict__ bh,
                       float* __restrict__ out) {
    __shared__ float xs[32 * 64];
    __shared__ float ws[64 * 32];
    int t = threadIdx.x;
    int gid = blockIdx.x * blockDim.x + t;
    if (gid < NN) g_cnt[gid] = 0;            // prep histogram for next call
    int node0 = blockIdx.x * 32;
    const float4* xsrc = (const float4*)(g_x + (size_t)node0 * 64);
    ((float4*)xs)[t]       = xsrc[t];
    ((float4*)xs)[t + 256] = xsrc[t + 256];
    ((float4*)ws)[t]       = ((const float4*)Wh)[t];
    ((float4*)ws)[t + 256] = ((const float4*)Wh)[t + 256];
    __syncthreads();
    int col = t & 31, nr = t >> 5;
    float a0, a1, a2, a3;
    a0 = a1 = a2 = a3 = bh[col];
#pragma unroll 8
    for (int kk = 0; kk < 64; kk++) {
        float w = ws[kk * 32 + col];
        a0 = fmaf(xs[nr * 64 + kk],        w, a0);
        a1 = fmaf(xs[(nr + 8) * 64 + kk],  w, a1);
        a2 = fmaf(xs[(nr + 16) * 64 + kk], w, a2);
        a3 = fmaf(xs[(nr + 24) * 64 + kk], w, a3);
    }
    out[(size_t)(node0 + nr) * 32 + col]      = a0;
    out[(size_t)(node0 + nr + 8) * 32 + col]  = a1;
    out[(size_t)(node0 + nr + 16) * 32 + col] = a2;
    out[(size_t)(node0 + nr + 24) * 32 + col] = a3;
}

// ================= launch =================
extern "C" void kernel_launch(void* const* d_in, const int* in_sizes, int n_in,
                              void* d_out, int out_size) {
    const float* x    = (const float*)d_in[0];
    const int*   ei   = (const int*)  d_in[1];
    const float* Wq   = (const float*)d_in[2];
    const float* bq   = (const float*)d_in[3];
    const float* Wk   = (const float*)d_in[4];
    const float* bk   = (const float*)d_in[5];
    const float* Wv   = (const float*)d_in[6];
    const float* bv   = (const float*)d_in[7];
    const float* Ws   = (const float*)d_in[8];
    const float* bs   = (const float*)d_in[9];
    const float* bn_g = (const float*)d_in[10];
    const float* bn_b = (const float*)d_in[11];
    const float* bn_m = (const float*)d_in[12];
    const float* bn_v = (const float*)d_in[13];
    const float* Wh   = (const float*)d_in[14];
    const float* bh   = (const float*)d_in[15];
    float* out = (float*)d_out;

    const int NB = (NN + 255) / 256;           // 391
    const int GA = (NN * 32 + 255) / 256;      // warp per node
    const int GH = NN / 32;                    // 3125

    uint4* wf_base;
    cudaGetSymbolAddress((void**)&wf_base, g_wf);

    k_prep1<<<EB + WPREPB, 256>>>(ei, Wq, Wk, Wv, Ws);            // 1: hist + wprep
    k_scan1<<<SBLK, 1024>>>();                                     // 2
    k_scan_fix<<<NB, 256>>>();                                     // 3
    k_gemm_fused<<<GR2, 256>>>(x, wf_base, bq, bk, bv, bs);        // 4: gemm L0 (profiled)
    k_scatter<<<EB, 256>>>(ei);                                    // 5
    k_attn<<<GA, 256>>>(bn_g, bn_b, bn_m, bn_v);                   // 6

    for (int l = 1; l < 3; l++) {
        size_t bo = (size_t)l * HID;
        k_gemm_fused<<<GR2, 256>>>(nullptr, wf_base + (size_t)l * 4096,
                                   bq + bo, bk + bo, bv + bo, bs + bo);
        k_attn<<<GA, 256>>>(bn_g + bo, bn_b + bo, bn_m + bo, bn_v + bo);
    }
    k_head<<<GH, 256>>>(Wh, bh, out);
}